// round 13
// baseline (speedup 1.0000x reference)
#include <cuda_runtime.h>
#include <cuda_bf16.h>
#include <math.h>
#include <stdint.h>

#define CC 48
#define NN 48
#define WW 24
#define RR 36
#define DD 1024
#define SS 256
#define MTOT (CC*NN*WW)   // 55296

// ---------------- scratch (device globals; no allocation allowed) ----------
__device__ __align__(16) __nv_bfloat16 g_smid[MTOT*SS];         // 28 MB
__device__ __align__(16) float g_smooth[MTOT];
__device__ __align__(16) __nv_bfloat16 g_qmb[(size_t)MTOT*DD];  // 113 MB
__device__ __align__(16) __nv_bfloat16 g_wc[(size_t)MTOT*DD];   // 113 MB
__device__ __align__(16) float g_fac[MTOT];
__device__ __align__(16) __nv_bfloat16 g_h[(size_t)MTOT*512];   // 56 MB
__device__ __align__(16) __nv_bfloat16 g_kt[(size_t)MTOT*SS];   // 28 MB
__device__ __align__(16) __nv_bfloat16 g_wbf[1507328];          // weights bf16
__device__ __align__(16) float g_higA[CC*NN*SS];
__device__ __align__(16) float g_higB[CC*NN*SS];

#define OFF_ALV0 0
#define OFF_ALV1 262144
#define OFF_MX2  524288
#define OFF_KW1  1048576
#define OFF_WMLP 1114112

__device__ __forceinline__ float warp_sum(float v) {
#pragma unroll
    for (int o = 16; o; o >>= 1) v += __shfl_xor_sync(0xffffffffu, v, o);
    return v;
}
__device__ __forceinline__ float warp_max(float v) {
#pragma unroll
    for (int o = 16; o; o >>= 1) v = fmaxf(v, __shfl_xor_sync(0xffffffffu, v, o));
    return v;
}
__device__ __forceinline__ uint32_t f2bf2(float lo, float hi) {
    uint32_t r; asm("cvt.rn.bf16x2.f32 %0, %1, %2;" : "=r"(r) : "f"(hi), "f"(lo)); return r;
}
__device__ __forceinline__ void ldsm4(uint32_t* r, uint32_t a) {
    asm volatile("ldmatrix.sync.aligned.m8n8.x4.shared.b16 {%0,%1,%2,%3},[%4];"
        : "=r"(r[0]),"=r"(r[1]),"=r"(r[2]),"=r"(r[3]) : "r"(a));
}
__device__ __forceinline__ void ldsm4t(uint32_t* r, uint32_t a) {
    asm volatile("ldmatrix.sync.aligned.m8n8.x4.trans.shared.b16 {%0,%1,%2,%3},[%4];"
        : "=r"(r[0]),"=r"(r[1]),"=r"(r[2]),"=r"(r[3]) : "r"(a));
}
__device__ __forceinline__ void mmabf(float* d, const uint32_t* a, const uint32_t* b) {
    asm volatile("mma.sync.aligned.m16n8k16.row.col.f32.bf16.bf16.f32 "
        "{%0,%1,%2,%3},{%4,%5,%6,%7},{%8,%9},{%0,%1,%2,%3};"
        : "+f"(d[0]),"+f"(d[1]),"+f"(d[2]),"+f"(d[3])
        : "r"(a[0]),"r"(a[1]),"r"(a[2]),"r"(a[3]),"r"(b[0]),"r"(b[1]));
}

// ---------------------------------------------------------------------------
// merged weight conversion (6 regions, one launch)
// ---------------------------------------------------------------------------
__global__ void cvtw_all(const float* __restrict__ alvw, const float* __restrict__ mxw2,
                         const float* __restrict__ kw,   const float* __restrict__ mxw1,
                         const float* __restrict__ smw1, __nv_bfloat16* __restrict__ wbf)
{
    int i = blockIdx.x * blockDim.x + threadIdx.x;
    const float* src; __nv_bfloat16* dst; int j; int ncols = 0, dstride = 0, dcol0 = 0;
    if (i < 131072)      { src = alvw;        dst = wbf + OFF_ALV0; j = i; }
    else if (i < 262144) { src = mxw2;        dst = wbf + OFF_MX2;  j = i - 131072; }
    else if (i < 278528) { src = kw + SS*SS;  dst = wbf + OFF_KW1;  j = i - 262144; }
    else if (i < 311296) { src = mxw1; dst = wbf + OFF_WMLP; j = i - 278528; ncols = 512; dstride = 896; dcol0 = 0; }
    else if (i < 319488) { src = smw1; dst = wbf + OFF_WMLP; j = i - 311296; ncols = 128; dstride = 896; dcol0 = 512; }
    else if (i < 335872) { src = kw;   dst = wbf + OFF_WMLP; j = i - 319488; ncols = 256; dstride = 896; dcol0 = 640; }
    else return;
    float4 v = *(const float4*)(src + (size_t)j*4);
    uint2 o; o.x = f2bf2(v.x, v.y); o.y = f2bf2(v.z, v.w);
    if (ncols == 0) {
        *(uint2*)(dst + (size_t)j*4) = o;
    } else {
        int row = (j*4) / ncols, col = (j*4) % ncols;
        *(uint2*)(dst + (size_t)row*dstride + dcol0 + col) = o;
    }
}

// ---------------------------------------------------------------------------
// bf16 m16n8k16 GEMM, 2-D warp tiling: 2 warps in M x 4 warps in N.
// AMODE 0: A fp32->cvt. 1: A=(cap-wc*fac)^2. 2: A bf16.
// EPI 0: +bias, l2norm full 256 row. EPI 1: +bias, tanh.
// EPI 2: +bias, tanh, clip(+1), *cap. EPI 3: fused MLP (h / smooth / kt).
// ---------------------------------------------------------------------------
template<int M_BLK,int N_BLK,int K_DIM,int N_TOT,int AMODE,int EPI,int OUTBF>
__global__ void __launch_bounds__(256) gemm_bf16(
    const float* __restrict__ Af, const __nv_bfloat16* __restrict__ Ab,
    const __nv_bfloat16* __restrict__ Bw,
    const float* __restrict__ bias, const float* __restrict__ bias2, const float* __restrict__ bias3,
    float* __restrict__ Cf, __nv_bfloat16* __restrict__ Cb,
    __nv_bfloat16* __restrict__ Cb2, __nv_bfloat16* __restrict__ Cb3,
    const float* __restrict__ cap, const float* __restrict__ fac)
{
    constexpr int MTW  = M_BLK/32;          // m16 tiles per warp (2 for M_BLK=64)
    constexpr int NTW  = N_BLK/32;          // n8 tiles per warp (4 for N128, 8 for N256)
    constexpr int SAW  = 20;
    constexpr int SBW  = N_BLK/2 + 4;
    constexpr int ABUF = M_BLK*SAW;
    constexpr int BBUF = 32*SBW;
    constexpr int APASS = M_BLK/32;
    constexpr int BROWP = 2048/N_BLK;
    constexpr int BPASS = 32/BROWP;
    constexpr int KT   = K_DIM/32;

    extern __shared__ uint32_t dsm[];
    uint32_t* As = dsm;
    uint32_t* Bs = dsm + 2*ABUF;
    float* sRed  = (float*)(dsm + 2*ABUF + 2*BBUF);   // M_BLK*4 used
    float* sFacR = sRed + M_BLK*8;

    const int m0 = blockIdx.y * M_BLK;
    const int n0 = blockIdx.x * N_BLK;
    const int tid = threadIdx.x, lane = tid & 31, wid = tid >> 5;
    const int g = lane >> 2, tig = lane & 3;
    const int wm = wid >> 2, wn = wid & 3;
    const int wn0 = wn * (N_BLK/4);

    const int a_row = tid >> 3, a_c = (tid & 7) * 4;
    float facr[APASS]; int caprow[APASS];
    if (AMODE == 1) {
#pragma unroll
        for (int p = 0; p < APASS; p++) {
            int r = m0 + p*32 + a_row;
            facr[p] = fac[r];
            caprow[p] = (r/1152)*24 + (r%24);
        }
    }
    const int b_row = tid / (N_BLK/8), b_c = (tid % (N_BLK/8)) * 8;
    const __nv_bfloat16* Bptr = Bw + (size_t)b_row*N_TOT + n0 + b_c;

    uint32_t areg[2*APASS]; uint4 breg[BPASS];

    auto loadA = [&](int kt) {
#pragma unroll
        for (int p = 0; p < APASS; p++) {
            int r = m0 + p*32 + a_row;
            if (AMODE == 2) {
                uint2 v = *(const uint2*)(Ab + (size_t)r*K_DIM + kt*32 + a_c);
                areg[p*2] = v.x; areg[p*2+1] = v.y;
            } else if (AMODE == 0) {
                float4 v = *(const float4*)(Af + (size_t)r*K_DIM + kt*32 + a_c);
                areg[p*2]   = f2bf2(v.x, v.y);
                areg[p*2+1] = f2bf2(v.z, v.w);
            } else {
                uint2 wv2 = *(const uint2*)(Ab + (size_t)r*K_DIM + kt*32 + a_c);
                float2 w01 = __bfloat1622float2(*(__nv_bfloat162*)&wv2.x);
                float2 w23 = __bfloat1622float2(*(__nv_bfloat162*)&wv2.y);
                float4 cv = *(const float4*)(cap + (size_t)caprow[p]*K_DIM + kt*32 + a_c);
                float f = facr[p];
                float s0 = cv.x - w01.x*f; s0 *= s0;
                float s1 = cv.y - w01.y*f; s1 *= s1;
                float s2 = cv.z - w23.x*f; s2 *= s2;
                float s3 = cv.w - w23.y*f; s3 *= s3;
                areg[p*2]   = f2bf2(s0, s1);
                areg[p*2+1] = f2bf2(s2, s3);
            }
        }
    };
    auto stsA = [&](int buf) {
#pragma unroll
        for (int p = 0; p < APASS; p++)
            *(uint2*)(As + buf*ABUF + (p*32 + a_row)*SAW + (tid&7)*2) =
                make_uint2(areg[p*2], areg[p*2+1]);
    };
    auto loadB = [&](int kt) {
#pragma unroll
        for (int p = 0; p < BPASS; p++)
            breg[p] = *(const uint4*)(Bptr + (size_t)(kt*32 + p*BROWP)*N_TOT);
    };
    auto stsB = [&](int buf) {
#pragma unroll
        for (int p = 0; p < BPASS; p++)
            *(uint4*)(Bs + buf*BBUF + (b_row + p*BROWP)*SBW + (tid % (N_BLK/8))*4) = breg[p];
    };

    loadA(0); loadB(0);
    stsA(0);  stsB(0);
    __syncthreads();

    float acc[MTW][NTW][4];
#pragma unroll
    for (int i = 0; i < MTW; i++)
#pragma unroll
        for (int j = 0; j < NTW; j++)
#pragma unroll
            for (int k = 0; k < 4; k++) acc[i][j][k] = 0.f;

    uint32_t smA = (uint32_t)__cvta_generic_to_shared(As);
    uint32_t smB = (uint32_t)__cvta_generic_to_shared(Bs);
    const uint32_t aoff = (wm*32 + (lane & 15))*(SAW*4) + (lane >> 4)*16;
    const uint32_t boff = ((lane & 7) + ((lane >> 3) & 1)*8)*(SBW*4)
                        + (wn0 + (lane >> 4)*8)*2;

    for (int kt = 0; kt < KT; kt++) {
        int cur = kt & 1;
        if (kt + 1 < KT) { loadA(kt+1); loadB(kt+1); }
        uint32_t Ab0 = smA + cur*(ABUF*4);
        uint32_t Bb0 = smB + cur*(BBUF*4);
#pragma unroll
        for (int ks = 0; ks < 2; ks++) {
            uint32_t af[MTW][4], bf[NTW][2];
#pragma unroll
            for (int i = 0; i < MTW; i++)
                ldsm4(af[i], Ab0 + i*16*(SAW*4) + aoff + ks*32);
#pragma unroll
            for (int jp = 0; jp < NTW/2; jp++) {
                uint32_t t[4];
                ldsm4t(t, Bb0 + ks*16*(SBW*4) + boff + jp*32);
                bf[2*jp][0] = t[0]; bf[2*jp][1] = t[1];
                bf[2*jp+1][0] = t[2]; bf[2*jp+1][1] = t[3];
            }
#pragma unroll
            for (int i = 0; i < MTW; i++)
#pragma unroll
                for (int j = 0; j < NTW; j++)
                    mmabf(acc[i][j], af[i], bf[j]);
        }
        if (kt + 1 < KT) { stsA((kt+1)&1); stsB((kt+1)&1); }
        __syncthreads();
    }

    if (EPI != 3) {
#pragma unroll
        for (int j = 0; j < NTW; j++) {
            int coln = n0 + wn0 + j*8 + 2*tig;
            float b0 = bias[coln], b1 = bias[coln+1];
#pragma unroll
            for (int i = 0; i < MTW; i++) {
                acc[i][j][0] += b0; acc[i][j][1] += b1;
                acc[i][j][2] += b0; acc[i][j][3] += b1;
            }
        }
    }

    if (EPI == 0) {
        float ps[MTW][2];
#pragma unroll
        for (int i = 0; i < MTW; i++) {
            ps[i][0] = 0.f; ps[i][1] = 0.f;
#pragma unroll
            for (int j = 0; j < NTW; j++) {
                ps[i][0] += acc[i][j][0]*acc[i][j][0] + acc[i][j][1]*acc[i][j][1];
                ps[i][1] += acc[i][j][2]*acc[i][j][2] + acc[i][j][3]*acc[i][j][3];
            }
        }
#pragma unroll
        for (int i = 0; i < MTW; i++)
#pragma unroll
            for (int h = 0; h < 2; h++) {
                ps[i][h] += __shfl_xor_sync(0xffffffffu, ps[i][h], 1);
                ps[i][h] += __shfl_xor_sync(0xffffffffu, ps[i][h], 2);
            }
        if (tig == 0) {
#pragma unroll
            for (int i = 0; i < MTW; i++) {
                sRed[(wm*32 + i*16 + g    )*4 + wn] = ps[i][0];
                sRed[(wm*32 + i*16 + g + 8)*4 + wn] = ps[i][1];
            }
        }
        __syncthreads();
        if (tid < M_BLK) {
            float s = sRed[tid*4] + sRed[tid*4+1] + sRed[tid*4+2] + sRed[tid*4+3];
            sFacR[tid] = 1.f / (sqrtf(s) + 1e-8f);
        }
        __syncthreads();
#pragma unroll
        for (int i = 0; i < MTW; i++) {
            int rl0 = wm*32 + i*16 + g, rl1 = rl0 + 8;
            float f0 = sFacR[rl0], f1 = sFacR[rl1];
#pragma unroll
            for (int j = 0; j < NTW; j++) {
                int coln = wn0 + j*8 + 2*tig;
                if (OUTBF) {
                    *(uint32_t*)&Cb[(size_t)(m0 + rl0)*N_TOT + coln] =
                        f2bf2(acc[i][j][0]*f0, acc[i][j][1]*f0);
                    *(uint32_t*)&Cb[(size_t)(m0 + rl1)*N_TOT + coln] =
                        f2bf2(acc[i][j][2]*f1, acc[i][j][3]*f1);
                } else {
                    *(float2*)&Cf[(size_t)(m0 + rl0)*N_TOT + coln] =
                        make_float2(acc[i][j][0]*f0, acc[i][j][1]*f0);
                    *(float2*)&Cf[(size_t)(m0 + rl1)*N_TOT + coln] =
                        make_float2(acc[i][j][2]*f1, acc[i][j][3]*f1);
                }
            }
        }
    } else if (EPI == 1) {
#pragma unroll
        for (int i = 0; i < MTW; i++) {
            int r0 = m0 + wm*32 + i*16 + g, r1 = r0 + 8;
#pragma unroll
            for (int j = 0; j < NTW; j++) {
                int coln = n0 + wn0 + j*8 + 2*tig;
                float v0 = tanhf(acc[i][j][0]), v1 = tanhf(acc[i][j][1]);
                float v2 = tanhf(acc[i][j][2]), v3 = tanhf(acc[i][j][3]);
                if (OUTBF) {
                    *(uint32_t*)&Cb[(size_t)r0*N_TOT + coln] = f2bf2(v0, v1);
                    *(uint32_t*)&Cb[(size_t)r1*N_TOT + coln] = f2bf2(v2, v3);
                } else {
                    *(float2*)&Cf[(size_t)r0*N_TOT + coln] = make_float2(v0, v1);
                    *(float2*)&Cf[(size_t)r1*N_TOT + coln] = make_float2(v2, v3);
                }
            }
        }
    } else if (EPI == 2) {
#pragma unroll
        for (int i = 0; i < MTW; i++) {
            int r0 = m0 + wm*32 + i*16 + g, r1 = r0 + 8;
            int cr0 = (r0/1152)*24 + (r0%24);
            int cr1 = (r1/1152)*24 + (r1%24);
#pragma unroll
            for (int j = 0; j < NTW; j++) {
                int coln = n0 + wn0 + j*8 + 2*tig;
                float m00 = fminf(fmaxf(tanhf(acc[i][j][0]) + 1.f, -1.f), 1.f);
                float m01 = fminf(fmaxf(tanhf(acc[i][j][1]) + 1.f, -1.f), 1.f);
                float m10 = fminf(fmaxf(tanhf(acc[i][j][2]) + 1.f, -1.f), 1.f);
                float m11 = fminf(fmaxf(tanhf(acc[i][j][3]) + 1.f, -1.f), 1.f);
                float2 c0 = *(const float2*)&cap[(size_t)cr0*DD + coln];
                float2 c1 = *(const float2*)&cap[(size_t)cr1*DD + coln];
                if (OUTBF) {
                    *(uint32_t*)&Cb[(size_t)r0*N_TOT + coln] = f2bf2(c0.x*m00, c0.y*m01);
                    *(uint32_t*)&Cb[(size_t)r1*N_TOT + coln] = f2bf2(c1.x*m10, c1.y*m11);
                } else {
                    *(float2*)&Cf[(size_t)r0*N_TOT + coln] = make_float2(c0.x*m00, c0.y*m01);
                    *(float2*)&Cf[(size_t)r1*N_TOT + coln] = make_float2(c1.x*m10, c1.y*m11);
                }
            }
        }
    } else {  // EPI 3
        if (n0 >= 512 && n0 < 640) {
            // smooth: x = tanh(acc + smb1); smooth = relu(x . smw2 + smb2 + 9)
            float pr[MTW][2];
#pragma unroll
            for (int i = 0; i < MTW; i++) { pr[i][0] = 0.f; pr[i][1] = 0.f; }
#pragma unroll
            for (int j = 0; j < NTW; j++) {
                int cl = (n0 - 512) + wn0 + j*8 + 2*tig;
                float b0 = bias2[cl], b1 = bias2[cl+1];
                float w0 = fac[cl],  w1 = fac[cl+1];
#pragma unroll
                for (int i = 0; i < MTW; i++) {
                    pr[i][0] += tanhf(acc[i][j][0] + b0)*w0 + tanhf(acc[i][j][1] + b1)*w1;
                    pr[i][1] += tanhf(acc[i][j][2] + b0)*w0 + tanhf(acc[i][j][3] + b1)*w1;
                }
            }
#pragma unroll
            for (int i = 0; i < MTW; i++)
#pragma unroll
                for (int h = 0; h < 2; h++) {
                    pr[i][h] += __shfl_xor_sync(0xffffffffu, pr[i][h], 1);
                    pr[i][h] += __shfl_xor_sync(0xffffffffu, pr[i][h], 2);
                }
            if (tig == 0) {
#pragma unroll
                for (int i = 0; i < MTW; i++) {
                    sRed[(wm*32 + i*16 + g    )*4 + wn] = pr[i][0];
                    sRed[(wm*32 + i*16 + g + 8)*4 + wn] = pr[i][1];
                }
            }
            __syncthreads();
            if (tid < M_BLK) {
                float s = sRed[tid*4] + sRed[tid*4+1] + sRed[tid*4+2] + sRed[tid*4+3];
                float v = s + cap[0] + 9.0f;
                Cf[m0 + tid] = v > 0.f ? v : 0.f;
            }
        } else {
            __nv_bfloat16* outp; const float* bp; int ostride, oc0;
            if (n0 < 512) { outp = Cb;  bp = bias;  ostride = 512; oc0 = n0; }
            else          { outp = Cb3; bp = bias3; ostride = 256; oc0 = n0 - 640; }
#pragma unroll
            for (int j = 0; j < NTW; j++) {
                int cl = oc0 + wn0 + j*8 + 2*tig;
                float b0 = bp[cl], b1 = bp[cl+1];
#pragma unroll
                for (int i = 0; i < MTW; i++) {
                    acc[i][j][0] += b0; acc[i][j][1] += b1;
                    acc[i][j][2] += b0; acc[i][j][3] += b1;
                }
            }
#pragma unroll
            for (int i = 0; i < MTW; i++) {
                int r0 = m0 + wm*32 + i*16 + g, r1 = r0 + 8;
#pragma unroll
                for (int j = 0; j < NTW; j++) {
                    int cl = oc0 + wn0 + j*8 + 2*tig;
                    *(uint32_t*)&outp[(size_t)r0*ostride + cl] =
                        f2bf2(tanhf(acc[i][j][0]), tanhf(acc[i][j][1]));
                    *(uint32_t*)&outp[(size_t)r1*ostride + cl] =
                        f2bf2(tanhf(acc[i][j][2]), tanhf(acc[i][j][3]));
                }
            }
        }
    }
}

// ---------------------------------------------------------------------------
// alv kernel: tensorized attn + wctx; parallelized fp32 softmax phases.
// ---------------------------------------------------------------------------
template<int PASS>
__global__ void __launch_bounds__(256) alv_kernel(
        const float* __restrict__ img, const float* __restrict__ cap,
        const int* __restrict__ lens)
{
    constexpr int ARS = 28;
    constexpr int IRS = 516;

    extern __shared__ float sm[];
    __nv_bfloat16* sImgBf = (__nv_bfloat16*)sm;            // 48 x 1032
    __nv_bfloat16* sQBf   = sImgBf + 48*1032;              // 32 x 1032
    float* sA   = (float*)(sQBf + 32*1032);                // RR*WW
    float* sAT  = sA + RR*WW;                              // WW*RR
    uint32_t* sAbfW = (uint32_t*)(sAT + WW*RR);            // 32*ARS
    float* sRed = (float*)(sAbfW + 32*ARS);                // 32*8
    __nv_bfloat16* sAbf = (__nv_bfloat16*)sAbfW;

    const int b = blockIdx.x;
    const int c = b / NN, n = b % NN;
    const int tid = threadIdx.x, lane = tid & 31, wid = tid >> 5;
    const int g = lane >> 2, tig = lane & 3;
    const int len = lens[c];

    {
        const float4* gi = (const float4*)(img + (size_t)n * RR * DD);
        for (int i = tid; i < RR*DD/4; i += 256) {
            float4 v = gi[i];
            int r = (i*4) >> 10, col = (i*4) & 1023;
            uint2 o; o.x = f2bf2(v.x, v.y); o.y = f2bf2(v.z, v.w);
            *(uint2*)(sImgBf + (size_t)r*1032 + col) = o;
        }
        for (int i = tid; i < 12*256; i += 256) {
            int r = 36 + i/256, col = (i%256)*4;
            *(uint2*)(sImgBf + (size_t)r*1032 + col) = make_uint2(0,0);
        }
        if (PASS == 0) {
            const float4* gq = (const float4*)(cap + (size_t)c * WW * DD);
            for (int i = tid; i < WW*DD/4; i += 256) {
                float4 v = gq[i];
                int r = (i*4) >> 10, col = (i*4) & 1023;
                uint2 o; o.x = f2bf2(v.x, v.y); o.y = f2bf2(v.z, v.w);
                *(uint2*)(sQBf + (size_t)r*1032 + col) = o;
            }
        } else {
            const uint2* gq = (const uint2*)(g_qmb + (size_t)b * WW * DD);
            for (int i = tid; i < WW*DD/4; i += 256) {
                int r = (i*4) >> 10, col = (i*4) & 1023;
                *(uint2*)(sQBf + (size_t)r*1032 + col) = gq[i];
            }
        }
        for (int i = tid; i < 8*256; i += 256) {
            int r = 24 + i/256, col = (i%256)*4;
            *(uint2*)(sQBf + (size_t)r*1032 + col) = make_uint2(0,0);
        }
        for (int i = tid; i < 32*ARS; i += 256) sAbfW[i] = 0;
    }
    __syncthreads();

    // attn via bf16 mma (warps 0-5)
    if (wid < 6) {
        int mi = wid >> 1, ni = wid & 1;
        uint32_t smI = (uint32_t)__cvta_generic_to_shared(sImgBf);
        uint32_t smQ = (uint32_t)__cvta_generic_to_shared(sQBf);
        uint32_t aBase = smI + (mi*16 + (lane & 15))*(IRS*4) + (lane >> 4)*16;
        uint32_t bBase = smQ + (ni*16 + (lane & 15))*(IRS*4) + (lane >> 4)*16;
        float acc0[4] = {0,0,0,0}, acc1[4] = {0,0,0,0};
#pragma unroll 4
        for (int kk = 0; kk < 64; kk++) {
            uint32_t a[4], t[4];
            ldsm4(a, aBase + kk*32);
            ldsm4(t, bBase + kk*32);
            uint32_t b0[2] = {t[0], t[2]};
            uint32_t b1[2] = {t[1], t[3]};
            mmabf(acc0, a, b0);
            mmabf(acc1, a, b1);
        }
        int r0 = mi*16 + g, r1 = r0 + 8;
        int w0 = ni*16 + 2*tig;
        if (r0 < RR) {
            if (w0 < WW)     sA[r0*WW + w0]     = acc0[0];
            if (w0+1 < WW)   sA[r0*WW + w0+1]   = acc0[1];
            if (w0+8 < WW)   sA[r0*WW + w0+8]   = acc1[0];
            if (w0+9 < WW)   sA[r0*WW + w0+9]   = acc1[1];
        }
        if (r1 < RR) {
            if (w0 < WW)     sA[r1*WW + w0]     = acc0[2];
            if (w0+1 < WW)   sA[r1*WW + w0+1]   = acc0[3];
            if (w0+8 < WW)   sA[r1*WW + w0+8]   = acc1[2];
            if (w0+9 < WW)   sA[r1*WW + w0+9]   = acc1[3];
        }
    }
    __syncthreads();

    // phase 2a: leaky relu + mask + l2norm over words. 4 threads per region.
    {
        int r = tid >> 2, q = tid & 3;
        float vals[6];
        float ss = 0.f;
        if (r < RR) {
#pragma unroll
            for (int k = 0; k < 6; k++) {
                int w = q + k*4;
                float v = sA[r*WW + w];
                v = (v >= 0.f) ? v : 0.1f * v;
                if (w >= len) v = 0.f;
                vals[k] = v;
                ss += v * v;
            }
        }
        ss += __shfl_xor_sync(0xffffffffu, ss, 1);
        ss += __shfl_xor_sync(0xffffffffu, ss, 2);
        if (r < RR) {
            float f = 1.f / (sqrtf(ss) + 1e-8f);
#pragma unroll
            for (int k = 0; k < 6; k++) sAT[(q + k*4)*RR + r] = vals[k] * f;
        }
    }
    __syncthreads();

    // phase 2b: softmax over regions -> bf16 A tile. 1 warp per 3 words.
    {
#pragma unroll
        for (int t = 0; t < 3; t++) {
            int w = wid*3 + t;
            float smo = (PASS == 0) ? 9.f : g_smooth[(size_t)b*WW + w];
            float v0 = (lane < RR)      ? sAT[w*RR + lane]      * smo : -1e30f;
            float v1 = (lane + 32 < RR) ? sAT[w*RR + lane + 32] * smo : -1e30f;
            float m = warp_max(fmaxf(v0, v1));
            float e0 = (lane < RR)      ? expf(v0 - m) : 0.f;
            float e1 = (lane + 32 < RR) ? expf(v1 - m) : 0.f;
            float s = warp_sum(e0 + e1);
            float inv = 1.f / s;
            if (lane < RR)      sAbf[w*(2*ARS) + lane]      = __float2bfloat16(e0 * inv);
            if (lane + 32 < RR) sAbf[w*(2*ARS) + lane + 32] = __float2bfloat16(e1 * inv);
        }
    }
    __syncthreads();

    // wctx = A(32x48) @ B(48x1024) via bf16 mma (8 warps)
    {
        uint32_t smAttn = (uint32_t)__cvta_generic_to_shared(sAbf);
        uint32_t smImgB = (uint32_t)__cvta_generic_to_shared(sImgBf);
        const uint32_t aoff = (lane & 15)*(ARS*4) + (lane >> 4)*16;
        const uint32_t bRowSel = ((lane & 7) + ((lane >> 3) & 1)*8)*(IRS*4);
        const uint32_t bColSel = (lane >> 4)*8;

        float psq[2][2] = {{0.f,0.f},{0.f,0.f}};
        for (int half = 0; half < 2; half++) {
            float acc[2][8][4];
#pragma unroll
            for (int i = 0; i < 2; i++)
#pragma unroll
                for (int j = 0; j < 8; j++)
#pragma unroll
                    for (int k = 0; k < 4; k++) acc[i][j][k] = 0.f;
#pragma unroll
            for (int ks = 0; ks < 3; ks++) {
                uint32_t af0[4], af1[4];
                ldsm4(af0, smAttn + aoff + ks*32);
                ldsm4(af1, smAttn + 16*(ARS*4) + aoff + ks*32);
#pragma unroll
                for (int jp = 0; jp < 4; jp++) {
                    int ncol = half*512 + wid*64 + jp*16 + bColSel;
                    uint32_t t[4];
                    ldsm4t(t, smImgB + ks*16*(IRS*4) + bRowSel + ncol*2);
                    mmabf(acc[0][2*jp],   af0, t);
                    mmabf(acc[0][2*jp+1], af0, t+2);
                    mmabf(acc[1][2*jp],   af1, t);
                    mmabf(acc[1][2*jp+1], af1, t+2);
                }
            }
#pragma unroll
            for (int i = 0; i < 2; i++) {
                int r0 = i*16 + g, r1 = r0 + 8;
#pragma unroll
                for (int j = 0; j < 8; j++) {
                    int coln = half*512 + wid*64 + j*8 + 2*tig;
                    float v0 = acc[i][j][0], v1 = acc[i][j][1];
                    float v2 = acc[i][j][2], v3 = acc[i][j][3];
                    psq[i][0] += v0*v0 + v1*v1;
                    psq[i][1] += v2*v2 + v3*v3;
                    if (r0 < WW)
                        *(uint32_t*)&g_wc[((size_t)b*WW + r0)*DD + coln] = f2bf2(v0, v1);
                    if (r1 < WW)
                        *(uint32_t*)&g_wc[((size_t)b*WW + r1)*DD + coln] = f2bf2(v2, v3);
                }
            }
        }
#pragma unroll
        for (int i = 0; i < 2; i++)
#pragma unroll
            for (int h = 0; h < 2; h++) {
                psq[i][h] += __shfl_xor_sync(0xffffffffu, psq[i][h], 1);
                psq[i][h] += __shfl_xor_sync(0xffffffffu, psq[i][h], 2);
            }
        if (tig == 0) {
#pragma unroll
            for (int i = 0; i < 2; i++) {
                sRed[(i*16 + g    )*8 + wid] = psq[i][0];
                sRed[(i*16 + g + 8)*8 + wid] = psq[i][1];
            }
        }
        __syncthreads();
        if (tid < WW) {
            float s = 0.f;
#pragma unroll
            for (int k = 0; k < 8; k++) s += sRed[tid*8 + k];
            g_fac[(size_t)b*WW + tid] = 1.f / (sqrtf(s) + 1e-8f);
        }
    }
}

// ---------------------------------------------------------------------------
// rar: dir==0 computes hig = masked mean of sim_mid in-kernel.
// ---------------------------------------------------------------------------
__global__ void __launch_bounds__(256) rar_kernel(
        const int* __restrict__ lens,
        const float* __restrict__ qw, const float* __restrict__ qb,
        const float* __restrict__ vw, const float* __restrict__ vb,
        const __nv_bfloat16* __restrict__ kt, int dir)
{
    extern __shared__ float sm[];
    __nv_bfloat16* sMid = (__nv_bfloat16*)sm;
    float* sHig = sm + WW*SS/2;
    float* sRed = sHig + SS;
    float* sLog = sRed + WW*8;
    float* sWgt = sLog + WW;
    float* sMisc= sWgt + WW;

    const int b = blockIdx.x;
    const int c = b / NN;
    const int tid = threadIdx.x, lane = tid & 31, wid = tid >> 5;
    const int len = lens[c];

    float* hout = (dir == 0) ? g_higB : g_higA;

    {
        const uint4* gm = (const uint4*)(g_smid + (size_t)b*WW*SS);
        uint4* s4 = (uint4*)sMid;
        for (int i = tid; i < WW*SS/8; i += 256) s4[i] = gm[i];
    }
    __syncthreads();

    if (dir == 0) {
        float s = 0.f;
        for (int w = 0; w < len; w++) s += __bfloat162float(sMid[w*SS + tid]);
        sHig[tid] = s / (float)len;
    } else {
        sHig[tid] = g_higB[(size_t)b*SS + tid];
    }
    __syncthreads();

    float hv;
    {
        float acc = qb[tid];
        const float* wp = qw + tid;
#pragma unroll 4
        for (int s0 = 0; s0 < SS/4; s0++) {
            float4 h4 = *(const float4*)(sHig + s0*4);
            acc = fmaf(h4.x, wp[(size_t)(s0*4+0)*SS], acc);
            acc = fmaf(h4.y, wp[(size_t)(s0*4+1)*SS], acc);
            acc = fmaf(h4.z, wp[(size_t)(s0*4+2)*SS], acc);
            acc = fmaf(h4.w, wp[(size_t)(s0*4+3)*SS], acc);
        }
        hv = tanhf(acc) * vw[tid];
    }

    {
        const __nv_bfloat16* ktp = kt + (size_t)b*WW*SS + tid;
        float pv[WW];
#pragma unroll
        for (int w = 0; w < WW; w++)
            pv[w] = __bfloat162float(ktp[(size_t)w*SS]) * hv;
#pragma unroll
        for (int w = 0; w < WW; w++) {
            float v = warp_sum(pv[w]);
            if (lane == 0) sRed[w*8 + wid] = v;
        }
    }
    __syncthreads();
    if (tid < WW) {
        float s = 0.f;
#pragma unroll
        for (int k = 0; k < 8; k++) s += sRed[tid*8 + k];
        s += vb[0];
        if (tid >= len) s = -1e30f;
        sLog[tid] = s;
    }
    __syncthreads();
    if (tid == 0) {
        float m = -1e30f;
        for (int w = 0; w < WW; w++) m = fmaxf(m, sLog[w]);
        float s = 0.f;
        for (int w = 0; w < WW; w++) { float e = expf(sLog[w] - m); sWgt[w] = e; s += e; }
        float inv = 1.f / s;
        for (int w = 0; w < WW; w++) sWgt[w] *= inv;
    }
    __syncthreads();

    float o = 0.f;
#pragma unroll
    for (int w = 0; w < WW; w++)
        o = fmaf(sWgt[w], __bfloat162float(sMid[w*SS + tid]), o);
    float sq = warp_sum(o * o);
    if (lane == 0) sRed[wid] = sq;
    __syncthreads();
    if (tid == 0) {
        float tot = 0.f;
#pragma unroll
        for (int k = 0; k < 8; k++) tot += sRed[k];
        sMisc[0] = 1.f / (sqrtf(tot) + 1e-8f);
    }
    __syncthreads();
    hout[(size_t)b*SS + tid] = o * sMisc[0];
}

// ---------------------------------------------------------------------------
__global__ void final_kernel(const float* __restrict__ ew, const float* __restrict__ eb,
                             float* __restrict__ out)
{
    int gw = (blockIdx.x * blockDim.x + threadIdx.x) >> 5;
    int lane = threadIdx.x & 31;
    int nwarps = (gridDim.x * blockDim.x) >> 5;
    for (int b = gw; b < CC*NN; b += nwarps) {
        const float* h = g_higA + (size_t)b*SS;
        float a = 0.f;
#pragma unroll
        for (int k = 0; k < 8; k++) a = fmaf(h[lane + k*32], ew[lane + k*32], a);
        a = warp_sum(a);
        if (lane == 0) {
            float v = a + eb[0];
            int c = b / NN, n = b % NN;
            out[n*CC + c] = 1.f / (1.f + expf(-v));
        }
    }
}

// ---------------------------------------------------------------------------
extern "C" void kernel_launch(void* const* d_in, const int* in_sizes, int n_in,
                              void* d_out, int out_size)
{
    const float* img  = (const float*)d_in[0];
    const float* cap  = (const float*)d_in[1];
    const int*   lens = (const int*)  d_in[2];
    const float* alvw = (const float*)d_in[3];
    const float* alvb = (const float*)d_in[4];
    const float* qw   = (const float*)d_in[5];
    const float* qb   = (const float*)d_in[6];
    const float* kw   = (const float*)d_in[7];
    const float* kb   = (const float*)d_in[8];
    const float* vw   = (const float*)d_in[9];
    const float* vb   = (const float*)d_in[10];
    const float* smw1 = (const float*)d_in[11];
    const float* smb1 = (const float*)d_in[12];
    const float* smw2 = (const float*)d_in[13];
    const float* smb2 = (const float*)d_in[14];
    const float* mxw1 = (const float*)d_in[15];
    const float* mxb1 = (const float*)d_in[16];
    const float* mxw2 = (const float*)d_in[17];
    const float* mxb2 = (const float*)d_in[18];
    const float* ew   = (const float*)d_in[19];
    const float* eb   = (const float*)d_in[20];
    float* out = (float*)d_out;

    float *pFac, *pSmooth;
    __nv_bfloat16 *pH, *pWbf, *pWc, *pKt, *pQm, *pSmid;
    cudaGetSymbolAddress((void**)&pSmid, g_smid);
    cudaGetSymbolAddress((void**)&pQm,  g_qmb);
    cudaGetSymbolAddress((void**)&pWc,  g_wc);
    cudaGetSymbolAddress((void**)&pFac, g_fac);
    cudaGetSymbolAddress((void**)&pH,   g_h);
    cudaGetSymbolAddress((void**)&pWbf, g_wbf);
    cudaGetSymbolAddress((void**)&pKt,  g_kt);
    cudaGetSymbolAddress((void**)&pSmooth, g_smooth);

    const size_t ALV_SMEM = (size_t)(48*1032 + 32*1032) * 2
                          + (size_t)(RR*WW*2 + 32*8) * 4 + 32*28*4;
    const size_t RAR_SMEM = (size_t)(WW*SS/2 + SS + WW*8 + WW + WW + 32) * sizeof(float);
    const size_t SM_N256 = (size_t)(2*64*20 + 2*32*132)*4 + (64*8 + 64)*4;
    const size_t SM_N128 = (size_t)(2*64*20 + 2*32*68)*4 + (64*8 + 64)*4;

    cudaFuncSetAttribute(alv_kernel<0>, cudaFuncAttributeMaxDynamicSharedMemorySize, (int)ALV_SMEM);
    cudaFuncSetAttribute(alv_kernel<1>, cudaFuncAttributeMaxDynamicSharedMemorySize, (int)ALV_SMEM);
    cudaFuncSetAttribute(gemm_bf16<64,256,1024,256,1,0,1>, cudaFuncAttributeMaxDynamicSharedMemorySize, (int)SM_N256);
    cudaFuncSetAttribute(gemm_bf16<64,128,256,896,2,3,1>,  cudaFuncAttributeMaxDynamicSharedMemorySize, (int)SM_N128);
    cudaFuncSetAttribute(gemm_bf16<64,256,512,1024,2,2,1>, cudaFuncAttributeMaxDynamicSharedMemorySize, (int)SM_N256);
    cudaFuncSetAttribute(gemm_bf16<64,256,256,256,2,1,1>,  cudaFuncAttributeMaxDynamicSharedMemorySize, (int)SM_N256);

    const int B = CC * NN;
    const int MB64 = MTOT / 64;

    cvtw_all<<<(335872 + 255)/256, 256>>>(alvw, mxw2, kw, mxw1, smw1, pWbf);

    // ---- pass 0 ----
    alv_kernel<0><<<B, 256, ALV_SMEM>>>(img, cap, lens);
    gemm_bf16<64,256,1024,256,1,0,1><<<dim3(1,MB64), 256, SM_N256>>>(
        nullptr, pWc, pWbf + OFF_ALV0, alvb, nullptr, nullptr,
        nullptr, pSmid, nullptr, nullptr, cap, pFac);
    gemm_bf16<64,128,256,896,2,3,1><<<dim3(7,MB64), 256, SM_N128>>>(
        nullptr, pSmid, pWbf + OFF_WMLP, mxb1, smb1, kb,
        pSmooth, pH, nullptr, pKt, smb2, smw2);
    gemm_bf16<64,256,512,1024,2,2,1><<<dim3(4,MB64), 256, SM_N256>>>(
        nullptr, pH, pWbf + OFF_MX2, mxb2, nullptr, nullptr,
        nullptr, pQm, nullptr, nullptr, cap, nullptr);
    rar_kernel<<<B, 256, RAR_SMEM>>>(lens, qw, qb, vw, vb, pKt, 0);

    // ---- pass 1 ----
    alv_kernel<1><<<B, 256, ALV_SMEM>>>(img, cap, lens);
    gemm_bf16<64,256,1024,256,1,0,1><<<dim3(1,MB64), 256, SM_N256>>>(
        nullptr, pWc, pWbf + OFF_ALV1, alvb + SS, nullptr, nullptr,
        nullptr, pSmid, nullptr, nullptr, cap, pFac);
    gemm_bf16<64,256,256,256,2,1,1><<<dim3(1,MB64), 256, SM_N256>>>(
        nullptr, pSmid, pWbf + OFF_KW1, kb + SS, nullptr, nullptr,
        nullptr, pKt, nullptr, nullptr, nullptr, nullptr);
    rar_kernel<<<B, 256, RAR_SMEM>>>(lens, qw + SS*SS, qb + SS, vw + SS, vb + 1, pKt, 1);

    final_kernel<<<9, 256>>>(ew, eb, out);
}

// round 14
// speedup vs baseline: 1.4646x; 1.4646x over previous
#include <cuda_runtime.h>
#include <cuda_bf16.h>
#include <math.h>
#include <stdint.h>

#define CC 48
#define NN 48
#define WW 24
#define RR 36
#define DD 1024
#define SS 256
#define MTOT (CC*NN*WW)   // 55296

// ---------------- scratch (device globals; no allocation allowed) ----------
__device__ __align__(16) __nv_bfloat16 g_smid[MTOT*SS];         // 28 MB
__device__ __align__(16) float g_smooth[MTOT];
__device__ __align__(16) __nv_bfloat16 g_qmb[(size_t)MTOT*DD];  // 113 MB
__device__ __align__(16) __nv_bfloat16 g_wc[(size_t)MTOT*DD];   // 113 MB
__device__ __align__(16) float g_fac[MTOT];
__device__ __align__(16) __nv_bfloat16 g_h[(size_t)MTOT*512];   // 56 MB
__device__ __align__(16) __nv_bfloat16 g_kt[(size_t)MTOT*SS];   // 28 MB
__device__ __align__(16) __nv_bfloat16 g_wbf[1507328];          // weights bf16
__device__ __align__(16) float g_higA[CC*NN*SS];
__device__ __align__(16) float g_higB[CC*NN*SS];

#define OFF_ALV0 0
#define OFF_ALV1 262144
#define OFF_MX2  524288
#define OFF_KW1  1048576
#define OFF_WMLP 1114112

__device__ __forceinline__ float warp_sum(float v) {
#pragma unroll
    for (int o = 16; o; o >>= 1) v += __shfl_xor_sync(0xffffffffu, v, o);
    return v;
}
__device__ __forceinline__ float warp_max(float v) {
#pragma unroll
    for (int o = 16; o; o >>= 1) v = fmaxf(v, __shfl_xor_sync(0xffffffffu, v, o));
    return v;
}
__device__ __forceinline__ uint32_t f2bf2(float lo, float hi) {
    uint32_t r; asm("cvt.rn.bf16x2.f32 %0, %1, %2;" : "=r"(r) : "f"(hi), "f"(lo)); return r;
}
__device__ __forceinline__ void ldsm4(uint32_t* r, uint32_t a) {
    asm volatile("ldmatrix.sync.aligned.m8n8.x4.shared.b16 {%0,%1,%2,%3},[%4];"
        : "=r"(r[0]),"=r"(r[1]),"=r"(r[2]),"=r"(r[3]) : "r"(a));
}
__device__ __forceinline__ void ldsm4t(uint32_t* r, uint32_t a) {
    asm volatile("ldmatrix.sync.aligned.m8n8.x4.trans.shared.b16 {%0,%1,%2,%3},[%4];"
        : "=r"(r[0]),"=r"(r[1]),"=r"(r[2]),"=r"(r[3]) : "r"(a));
}
__device__ __forceinline__ void mmabf(float* d, const uint32_t* a, const uint32_t* b) {
    asm volatile("mma.sync.aligned.m16n8k16.row.col.f32.bf16.bf16.f32 "
        "{%0,%1,%2,%3},{%4,%5,%6,%7},{%8,%9},{%0,%1,%2,%3};"
        : "+f"(d[0]),"+f"(d[1]),"+f"(d[2]),"+f"(d[3])
        : "r"(a[0]),"r"(a[1]),"r"(a[2]),"r"(a[3]),"r"(b[0]),"r"(b[1]));
}

// ---------------------------------------------------------------------------
// merged weight conversion (6 regions, one launch)
// ---------------------------------------------------------------------------
__global__ void cvtw_all(const float* __restrict__ alvw, const float* __restrict__ mxw2,
                         const float* __restrict__ kw,   const float* __restrict__ mxw1,
                         const float* __restrict__ smw1, __nv_bfloat16* __restrict__ wbf)
{
    int i = blockIdx.x * blockDim.x + threadIdx.x;
    const float* src; __nv_bfloat16* dst; int j; int ncols = 0, dstride = 0, dcol0 = 0;
    if (i < 131072)      { src = alvw;        dst = wbf + OFF_ALV0; j = i; }
    else if (i < 262144) { src = mxw2;        dst = wbf + OFF_MX2;  j = i - 131072; }
    else if (i < 278528) { src = kw + SS*SS;  dst = wbf + OFF_KW1;  j = i - 262144; }
    else if (i < 311296) { src = mxw1; dst = wbf + OFF_WMLP; j = i - 278528; ncols = 512; dstride = 896; dcol0 = 0; }
    else if (i < 319488) { src = smw1; dst = wbf + OFF_WMLP; j = i - 311296; ncols = 128; dstride = 896; dcol0 = 512; }
    else if (i < 335872) { src = kw;   dst = wbf + OFF_WMLP; j = i - 319488; ncols = 256; dstride = 896; dcol0 = 640; }
    else return;
    float4 v = *(const float4*)(src + (size_t)j*4);
    uint2 o; o.x = f2bf2(v.x, v.y); o.y = f2bf2(v.z, v.w);
    if (ncols == 0) {
        *(uint2*)(dst + (size_t)j*4) = o;
    } else {
        int row = (j*4) / ncols, col = (j*4) % ncols;
        *(uint2*)(dst + (size_t)row*dstride + dcol0 + col) = o;
    }
}

// ---------------------------------------------------------------------------
// bf16 m16n8k16 GEMM — R11 proven 1-D warp tiling (8 warps split N).
// AMODE 0: A fp32->cvt. 1: A=(cap-wc*fac)^2. 2: A bf16.
// EPI 0: +bias, l2norm full 256 row. EPI 1: +bias, tanh.
// EPI 2: +bias, tanh, clip(+1), *cap. EPI 3: fused MLP (h / smooth / kt).
// ---------------------------------------------------------------------------
template<int M_BLK,int N_BLK,int K_DIM,int N_TOT,int AMODE,int EPI,int OUTBF>
__global__ void __launch_bounds__(256) gemm_bf16(
    const float* __restrict__ Af, const __nv_bfloat16* __restrict__ Ab,
    const __nv_bfloat16* __restrict__ Bw,
    const float* __restrict__ bias, const float* __restrict__ bias2, const float* __restrict__ bias3,
    float* __restrict__ Cf, __nv_bfloat16* __restrict__ Cb,
    __nv_bfloat16* __restrict__ Cb2, __nv_bfloat16* __restrict__ Cb3,
    const float* __restrict__ cap, const float* __restrict__ fac)
{
    constexpr int MT   = M_BLK/16;
    constexpr int NT   = N_BLK/64;
    constexpr int SAW  = 20;
    constexpr int SBW  = N_BLK/2 + 4;
    constexpr int ABUF = M_BLK*SAW;
    constexpr int BBUF = 32*SBW;
    constexpr int APASS = M_BLK/32;
    constexpr int BROWP = 2048/N_BLK;
    constexpr int BPASS = 32/BROWP;
    constexpr int KT   = K_DIM/32;

    extern __shared__ uint32_t dsm[];
    uint32_t* As = dsm;
    uint32_t* Bs = dsm + 2*ABUF;
    float* sRed  = (float*)(dsm + 2*ABUF + 2*BBUF);
    float* sFacR = sRed + M_BLK*8;

    const int m0 = blockIdx.y * M_BLK;
    const int n0 = blockIdx.x * N_BLK;
    const int tid = threadIdx.x, lane = tid & 31, wid = tid >> 5;
    const int g = lane >> 2, tig = lane & 3;
    const int wn0 = wid * (N_BLK/8);

    const int a_row = tid >> 3, a_c = (tid & 7) * 4;
    float facr[APASS]; int caprow[APASS];
    if (AMODE == 1) {
#pragma unroll
        for (int p = 0; p < APASS; p++) {
            int r = m0 + p*32 + a_row;
            facr[p] = fac[r];
            caprow[p] = (r/1152)*24 + (r%24);
        }
    }
    const int b_row = tid / (N_BLK/8), b_c = (tid % (N_BLK/8)) * 8;
    const __nv_bfloat16* Bptr = Bw + (size_t)b_row*N_TOT + n0 + b_c;

    uint32_t areg[2*APASS]; uint4 breg[BPASS];

    auto loadA = [&](int kt) {
#pragma unroll
        for (int p = 0; p < APASS; p++) {
            int r = m0 + p*32 + a_row;
            if (AMODE == 2) {
                uint2 v = *(const uint2*)(Ab + (size_t)r*K_DIM + kt*32 + a_c);
                areg[p*2] = v.x; areg[p*2+1] = v.y;
            } else if (AMODE == 0) {
                float4 v = *(const float4*)(Af + (size_t)r*K_DIM + kt*32 + a_c);
                areg[p*2]   = f2bf2(v.x, v.y);
                areg[p*2+1] = f2bf2(v.z, v.w);
            } else {
                uint2 wv2 = *(const uint2*)(Ab + (size_t)r*K_DIM + kt*32 + a_c);
                float2 w01 = __bfloat1622float2(*(__nv_bfloat162*)&wv2.x);
                float2 w23 = __bfloat1622float2(*(__nv_bfloat162*)&wv2.y);
                float4 cv = *(const float4*)(cap + (size_t)caprow[p]*K_DIM + kt*32 + a_c);
                float f = facr[p];
                float s0 = cv.x - w01.x*f; s0 *= s0;
                float s1 = cv.y - w01.y*f; s1 *= s1;
                float s2 = cv.z - w23.x*f; s2 *= s2;
                float s3 = cv.w - w23.y*f; s3 *= s3;
                areg[p*2]   = f2bf2(s0, s1);
                areg[p*2+1] = f2bf2(s2, s3);
            }
        }
    };
    auto stsA = [&](int buf) {
#pragma unroll
        for (int p = 0; p < APASS; p++)
            *(uint2*)(As + buf*ABUF + (p*32 + a_row)*SAW + (tid&7)*2) =
                make_uint2(areg[p*2], areg[p*2+1]);
    };
    auto loadB = [&](int kt) {
#pragma unroll
        for (int p = 0; p < BPASS; p++)
            breg[p] = *(const uint4*)(Bptr + (size_t)(kt*32 + p*BROWP)*N_TOT);
    };
    auto stsB = [&](int buf) {
#pragma unroll
        for (int p = 0; p < BPASS; p++)
            *(uint4*)(Bs + buf*BBUF + (b_row + p*BROWP)*SBW + (tid % (N_BLK/8))*4) = breg[p];
    };

    loadA(0); loadB(0);
    stsA(0);  stsB(0);
    __syncthreads();

    float acc[MT][NT][4];
#pragma unroll
    for (int i = 0; i < MT; i++)
#pragma unroll
        for (int j = 0; j < NT; j++)
#pragma unroll
            for (int k = 0; k < 4; k++) acc[i][j][k] = 0.f;

    uint32_t smA = (uint32_t)__cvta_generic_to_shared(As);
    uint32_t smB = (uint32_t)__cvta_generic_to_shared(Bs);
    const uint32_t aoff = (lane & 15)*(SAW*4) + (lane >> 4)*16;
    const uint32_t boff = ((lane & 7) + ((lane >> 3) & 1)*8)*(SBW*4)
                        + (wn0 + (lane >> 4)*8)*2;

    for (int kt = 0; kt < KT; kt++) {
        int cur = kt & 1;
        if (kt + 1 < KT) { loadA(kt+1); loadB(kt+1); }
        uint32_t Ab0 = smA + cur*(ABUF*4);
        uint32_t Bb0 = smB + cur*(BBUF*4);
#pragma unroll
        for (int ks = 0; ks < 2; ks++) {
            uint32_t af[MT][4], bf[NT][2];
#pragma unroll
            for (int i = 0; i < MT; i++)
                ldsm4(af[i], Ab0 + i*16*(SAW*4) + aoff + ks*32);
#pragma unroll
            for (int jp = 0; jp < NT/2; jp++) {
                uint32_t t[4];
                ldsm4t(t, Bb0 + ks*16*(SBW*4) + boff + jp*32);
                bf[2*jp][0] = t[0]; bf[2*jp][1] = t[1];
                bf[2*jp+1][0] = t[2]; bf[2*jp+1][1] = t[3];
            }
#pragma unroll
            for (int i = 0; i < MT; i++)
#pragma unroll
                for (int j = 0; j < NT; j++)
                    mmabf(acc[i][j], af[i], bf[j]);
        }
        if (kt + 1 < KT) { stsA((kt+1)&1); stsB((kt+1)&1); }
        __syncthreads();
    }

    if (EPI != 3) {
#pragma unroll
        for (int j = 0; j < NT; j++) {
            int coln = n0 + wn0 + j*8 + 2*tig;
            float b0 = bias[coln], b1 = bias[coln+1];
#pragma unroll
            for (int i = 0; i < MT; i++) {
                acc[i][j][0] += b0; acc[i][j][1] += b1;
                acc[i][j][2] += b0; acc[i][j][3] += b1;
            }
        }
    }

    if (EPI == 0) {
        float ps[MT][2];
#pragma unroll
        for (int i = 0; i < MT; i++) {
            ps[i][0] = 0.f; ps[i][1] = 0.f;
#pragma unroll
            for (int j = 0; j < NT; j++) {
                ps[i][0] += acc[i][j][0]*acc[i][j][0] + acc[i][j][1]*acc[i][j][1];
                ps[i][1] += acc[i][j][2]*acc[i][j][2] + acc[i][j][3]*acc[i][j][3];
            }
        }
#pragma unroll
        for (int i = 0; i < MT; i++)
#pragma unroll
            for (int h = 0; h < 2; h++) {
                ps[i][h] += __shfl_xor_sync(0xffffffffu, ps[i][h], 1);
                ps[i][h] += __shfl_xor_sync(0xffffffffu, ps[i][h], 2);
            }
        if (tig == 0) {
#pragma unroll
            for (int i = 0; i < MT; i++) {
                sRed[(i*16 + g    )*8 + wid] = ps[i][0];
                sRed[(i*16 + g + 8)*8 + wid] = ps[i][1];
            }
        }
        __syncthreads();
        if (tid < M_BLK) {
            float s = 0.f;
#pragma unroll
            for (int k = 0; k < 8; k++) s += sRed[tid*8 + k];
            sFacR[tid] = 1.f / (sqrtf(s) + 1e-8f);
        }
        __syncthreads();
#pragma unroll
        for (int i = 0; i < MT; i++) {
            float f0 = sFacR[i*16 + g], f1 = sFacR[i*16 + g + 8];
#pragma unroll
            for (int j = 0; j < NT; j++) {
                int coln = wn0 + j*8 + 2*tig;
                if (OUTBF) {
                    *(uint32_t*)&Cb[(size_t)(m0 + i*16 + g    )*N_TOT + coln] =
                        f2bf2(acc[i][j][0]*f0, acc[i][j][1]*f0);
                    *(uint32_t*)&Cb[(size_t)(m0 + i*16 + g + 8)*N_TOT + coln] =
                        f2bf2(acc[i][j][2]*f1, acc[i][j][3]*f1);
                } else {
                    *(float2*)&Cf[(size_t)(m0 + i*16 + g    )*N_TOT + coln] =
                        make_float2(acc[i][j][0]*f0, acc[i][j][1]*f0);
                    *(float2*)&Cf[(size_t)(m0 + i*16 + g + 8)*N_TOT + coln] =
                        make_float2(acc[i][j][2]*f1, acc[i][j][3]*f1);
                }
            }
        }
    } else if (EPI == 1) {
#pragma unroll
        for (int i = 0; i < MT; i++) {
            int r0 = m0 + i*16 + g, r1 = r0 + 8;
#pragma unroll
            for (int j = 0; j < NT; j++) {
                int coln = n0 + wn0 + j*8 + 2*tig;
                float v0 = tanhf(acc[i][j][0]), v1 = tanhf(acc[i][j][1]);
                float v2 = tanhf(acc[i][j][2]), v3 = tanhf(acc[i][j][3]);
                if (OUTBF) {
                    *(uint32_t*)&Cb[(size_t)r0*N_TOT + coln] = f2bf2(v0, v1);
                    *(uint32_t*)&Cb[(size_t)r1*N_TOT + coln] = f2bf2(v2, v3);
                } else {
                    *(float2*)&Cf[(size_t)r0*N_TOT + coln] = make_float2(v0, v1);
                    *(float2*)&Cf[(size_t)r1*N_TOT + coln] = make_float2(v2, v3);
                }
            }
        }
    } else if (EPI == 2) {
#pragma unroll
        for (int i = 0; i < MT; i++) {
            int r0 = m0 + i*16 + g, r1 = r0 + 8;
            int cr0 = (r0/1152)*24 + (r0%24);
            int cr1 = (r1/1152)*24 + (r1%24);
#pragma unroll
            for (int j = 0; j < NT; j++) {
                int coln = n0 + wn0 + j*8 + 2*tig;
                float m00 = fminf(fmaxf(tanhf(acc[i][j][0]) + 1.f, -1.f), 1.f);
                float m01 = fminf(fmaxf(tanhf(acc[i][j][1]) + 1.f, -1.f), 1.f);
                float m10 = fminf(fmaxf(tanhf(acc[i][j][2]) + 1.f, -1.f), 1.f);
                float m11 = fminf(fmaxf(tanhf(acc[i][j][3]) + 1.f, -1.f), 1.f);
                float2 c0 = *(const float2*)&cap[(size_t)cr0*DD + coln];
                float2 c1 = *(const float2*)&cap[(size_t)cr1*DD + coln];
                if (OUTBF) {
                    *(uint32_t*)&Cb[(size_t)r0*N_TOT + coln] = f2bf2(c0.x*m00, c0.y*m01);
                    *(uint32_t*)&Cb[(size_t)r1*N_TOT + coln] = f2bf2(c1.x*m10, c1.y*m11);
                } else {
                    *(float2*)&Cf[(size_t)r0*N_TOT + coln] = make_float2(c0.x*m00, c0.y*m01);
                    *(float2*)&Cf[(size_t)r1*N_TOT + coln] = make_float2(c1.x*m10, c1.y*m11);
                }
            }
        }
    } else {  // EPI 3
        if (n0 >= 512 && n0 < 640) {
            float pr[MT][2];
#pragma unroll
            for (int i = 0; i < MT; i++) { pr[i][0] = 0.f; pr[i][1] = 0.f; }
#pragma unroll
            for (int j = 0; j < NT; j++) {
                int cl = (n0 - 512) + wn0 + j*8 + 2*tig;
                float b0 = bias2[cl], b1 = bias2[cl+1];
                float w0 = fac[cl],  w1 = fac[cl+1];
#pragma unroll
                for (int i = 0; i < MT; i++) {
                    pr[i][0] += tanhf(acc[i][j][0] + b0)*w0 + tanhf(acc[i][j][1] + b1)*w1;
                    pr[i][1] += tanhf(acc[i][j][2] + b0)*w0 + tanhf(acc[i][j][3] + b1)*w1;
                }
            }
#pragma unroll
            for (int i = 0; i < MT; i++)
#pragma unroll
                for (int h = 0; h < 2; h++) {
                    pr[i][h] += __shfl_xor_sync(0xffffffffu, pr[i][h], 1);
                    pr[i][h] += __shfl_xor_sync(0xffffffffu, pr[i][h], 2);
                }
            if (tig == 0) {
#pragma unroll
                for (int i = 0; i < MT; i++) {
                    sRed[(i*16 + g    )*8 + wid] = pr[i][0];
                    sRed[(i*16 + g + 8)*8 + wid] = pr[i][1];
                }
            }
            __syncthreads();
            if (tid < M_BLK) {
                float s = 0.f;
#pragma unroll
                for (int k = 0; k < 8; k++) s += sRed[tid*8 + k];
                float v = s + cap[0] + 9.0f;
                Cf[m0 + tid] = v > 0.f ? v : 0.f;
            }
        } else {
            __nv_bfloat16* outp; const float* bp; int ostride, oc0;
            if (n0 < 512) { outp = Cb;  bp = bias;  ostride = 512; oc0 = n0; }
            else          { outp = Cb3; bp = bias3; ostride = 256; oc0 = n0 - 640; }
#pragma unroll
            for (int j = 0; j < NT; j++) {
                int cl = oc0 + wn0 + j*8 + 2*tig;
                float b0 = bp[cl], b1 = bp[cl+1];
#pragma unroll
                for (int i = 0; i < MT; i++) {
                    acc[i][j][0] += b0; acc[i][j][1] += b1;
                    acc[i][j][2] += b0; acc[i][j][3] += b1;
                }
            }
#pragma unroll
            for (int i = 0; i < MT; i++) {
                int r0 = m0 + i*16 + g, r1 = r0 + 8;
#pragma unroll
                for (int j = 0; j < NT; j++) {
                    int cl = oc0 + wn0 + j*8 + 2*tig;
                    *(uint32_t*)&outp[(size_t)r0*ostride + cl] =
                        f2bf2(tanhf(acc[i][j][0]), tanhf(acc[i][j][1]));
                    *(uint32_t*)&outp[(size_t)r1*ostride + cl] =
                        f2bf2(tanhf(acc[i][j][2]), tanhf(acc[i][j][3]));
                }
            }
        }
    }
}

// ---------------------------------------------------------------------------
// alv kernel: tensorized attn + wctx; parallelized fp32 softmax phases.
// ---------------------------------------------------------------------------
template<int PASS>
__global__ void __launch_bounds__(256) alv_kernel(
        const float* __restrict__ img, const float* __restrict__ cap,
        const int* __restrict__ lens)
{
    constexpr int ARS = 28;
    constexpr int IRS = 516;

    extern __shared__ float sm[];
    __nv_bfloat16* sImgBf = (__nv_bfloat16*)sm;            // 48 x 1032
    __nv_bfloat16* sQBf   = sImgBf + 48*1032;              // 32 x 1032
    float* sA   = (float*)(sQBf + 32*1032);                // RR*WW
    float* sAT  = sA + RR*WW;                              // WW*RR
    uint32_t* sAbfW = (uint32_t*)(sAT + WW*RR);            // 32*ARS
    float* sRed = (float*)(sAbfW + 32*ARS);                // 32*8
    __nv_bfloat16* sAbf = (__nv_bfloat16*)sAbfW;

    const int b = blockIdx.x;
    const int c = b / NN, n = b % NN;
    const int tid = threadIdx.x, lane = tid & 31, wid = tid >> 5;
    const int g = lane >> 2, tig = lane & 3;
    const int len = lens[c];

    {
        const float4* gi = (const float4*)(img + (size_t)n * RR * DD);
        for (int i = tid; i < RR*DD/4; i += 256) {
            float4 v = gi[i];
            int r = (i*4) >> 10, col = (i*4) & 1023;
            uint2 o; o.x = f2bf2(v.x, v.y); o.y = f2bf2(v.z, v.w);
            *(uint2*)(sImgBf + (size_t)r*1032 + col) = o;
        }
        for (int i = tid; i < 12*256; i += 256) {
            int r = 36 + i/256, col = (i%256)*4;
            *(uint2*)(sImgBf + (size_t)r*1032 + col) = make_uint2(0,0);
        }
        if (PASS == 0) {
            const float4* gq = (const float4*)(cap + (size_t)c * WW * DD);
            for (int i = tid; i < WW*DD/4; i += 256) {
                float4 v = gq[i];
                int r = (i*4) >> 10, col = (i*4) & 1023;
                uint2 o; o.x = f2bf2(v.x, v.y); o.y = f2bf2(v.z, v.w);
                *(uint2*)(sQBf + (size_t)r*1032 + col) = o;
            }
        } else {
            const uint2* gq = (const uint2*)(g_qmb + (size_t)b * WW * DD);
            for (int i = tid; i < WW*DD/4; i += 256) {
                int r = (i*4) >> 10, col = (i*4) & 1023;
                *(uint2*)(sQBf + (size_t)r*1032 + col) = gq[i];
            }
        }
        for (int i = tid; i < 8*256; i += 256) {
            int r = 24 + i/256, col = (i%256)*4;
            *(uint2*)(sQBf + (size_t)r*1032 + col) = make_uint2(0,0);
        }
        for (int i = tid; i < 32*ARS; i += 256) sAbfW[i] = 0;
    }
    __syncthreads();

    // attn via bf16 mma (warps 0-5)
    if (wid < 6) {
        int mi = wid >> 1, ni = wid & 1;
        uint32_t smI = (uint32_t)__cvta_generic_to_shared(sImgBf);
        uint32_t smQ = (uint32_t)__cvta_generic_to_shared(sQBf);
        uint32_t aBase = smI + (mi*16 + (lane & 15))*(IRS*4) + (lane >> 4)*16;
        uint32_t bBase = smQ + (ni*16 + (lane & 15))*(IRS*4) + (lane >> 4)*16;
        float acc0[4] = {0,0,0,0}, acc1[4] = {0,0,0,0};
#pragma unroll 4
        for (int kk = 0; kk < 64; kk++) {
            uint32_t a[4], t[4];
            ldsm4(a, aBase + kk*32);
            ldsm4(t, bBase + kk*32);
            uint32_t b0[2] = {t[0], t[2]};
            uint32_t b1[2] = {t[1], t[3]};
            mmabf(acc0, a, b0);
            mmabf(acc1, a, b1);
        }
        int r0 = mi*16 + g, r1 = r0 + 8;
        int w0 = ni*16 + 2*tig;
        if (r0 < RR) {
            if (w0 < WW)     sA[r0*WW + w0]     = acc0[0];
            if (w0+1 < WW)   sA[r0*WW + w0+1]   = acc0[1];
            if (w0+8 < WW)   sA[r0*WW + w0+8]   = acc1[0];
            if (w0+9 < WW)   sA[r0*WW + w0+9]   = acc1[1];
        }
        if (r1 < RR) {
            if (w0 < WW)     sA[r1*WW + w0]     = acc0[2];
            if (w0+1 < WW)   sA[r1*WW + w0+1]   = acc0[3];
            if (w0+8 < WW)   sA[r1*WW + w0+8]   = acc1[2];
            if (w0+9 < WW)   sA[r1*WW + w0+9]   = acc1[3];
        }
    }
    __syncthreads();

    // phase 2a: leaky relu + mask + l2norm over words. 4 threads per region.
    {
        int r = tid >> 2, q = tid & 3;
        float vals[6];
        float ss = 0.f;
        if (r < RR) {
#pragma unroll
            for (int k = 0; k < 6; k++) {
                int w = q + k*4;
                float v = sA[r*WW + w];
                v = (v >= 0.f) ? v : 0.1f * v;
                if (w >= len) v = 0.f;
                vals[k] = v;
                ss += v * v;
            }
        }
        ss += __shfl_xor_sync(0xffffffffu, ss, 1);
        ss += __shfl_xor_sync(0xffffffffu, ss, 2);
        if (r < RR) {
            float f = 1.f / (sqrtf(ss) + 1e-8f);
#pragma unroll
            for (int k = 0; k < 6; k++) sAT[(q + k*4)*RR + r] = vals[k] * f;
        }
    }
    __syncthreads();

    // phase 2b: softmax over regions -> bf16 A tile. 1 warp per 3 words.
    {
#pragma unroll
        for (int t = 0; t < 3; t++) {
            int w = wid*3 + t;
            float smo = (PASS == 0) ? 9.f : g_smooth[(size_t)b*WW + w];
            float v0 = (lane < RR)      ? sAT[w*RR + lane]      * smo : -1e30f;
            float v1 = (lane + 32 < RR) ? sAT[w*RR + lane + 32] * smo : -1e30f;
            float m = warp_max(fmaxf(v0, v1));
            float e0 = (lane < RR)      ? expf(v0 - m) : 0.f;
            float e1 = (lane + 32 < RR) ? expf(v1 - m) : 0.f;
            float s = warp_sum(e0 + e1);
            float inv = 1.f / s;
            if (lane < RR)      sAbf[w*(2*ARS) + lane]      = __float2bfloat16(e0 * inv);
            if (lane + 32 < RR) sAbf[w*(2*ARS) + lane + 32] = __float2bfloat16(e1 * inv);
        }
    }
    __syncthreads();

    // wctx = A(32x48) @ B(48x1024) via bf16 mma (8 warps)
    {
        uint32_t smAttn = (uint32_t)__cvta_generic_to_shared(sAbf);
        uint32_t smImgB = (uint32_t)__cvta_generic_to_shared(sImgBf);
        const uint32_t aoff = (lane & 15)*(ARS*4) + (lane >> 4)*16;
        const uint32_t bRowSel = ((lane & 7) + ((lane >> 3) & 1)*8)*(IRS*4);
        const uint32_t bColSel = (lane >> 4)*8;

        float psq[2][2] = {{0.f,0.f},{0.f,0.f}};
        for (int half = 0; half < 2; half++) {
            float acc[2][8][4];
#pragma unroll
            for (int i = 0; i < 2; i++)
#pragma unroll
                for (int j = 0; j < 8; j++)
#pragma unroll
                    for (int k = 0; k < 4; k++) acc[i][j][k] = 0.f;
#pragma unroll
            for (int ks = 0; ks < 3; ks++) {
                uint32_t af0[4], af1[4];
                ldsm4(af0, smAttn + aoff + ks*32);
                ldsm4(af1, smAttn + 16*(ARS*4) + aoff + ks*32);
#pragma unroll
                for (int jp = 0; jp < 4; jp++) {
                    int ncol = half*512 + wid*64 + jp*16 + bColSel;
                    uint32_t t[4];
                    ldsm4t(t, smImgB + ks*16*(IRS*4) + bRowSel + ncol*2);
                    mmabf(acc[0][2*jp],   af0, t);
                    mmabf(acc[0][2*jp+1], af0, t+2);
                    mmabf(acc[1][2*jp],   af1, t);
                    mmabf(acc[1][2*jp+1], af1, t+2);
                }
            }
#pragma unroll
            for (int i = 0; i < 2; i++) {
                int r0 = i*16 + g, r1 = r0 + 8;
#pragma unroll
                for (int j = 0; j < 8; j++) {
                    int coln = half*512 + wid*64 + j*8 + 2*tig;
                    float v0 = acc[i][j][0], v1 = acc[i][j][1];
                    float v2 = acc[i][j][2], v3 = acc[i][j][3];
                    psq[i][0] += v0*v0 + v1*v1;
                    psq[i][1] += v2*v2 + v3*v3;
                    if (r0 < WW)
                        *(uint32_t*)&g_wc[((size_t)b*WW + r0)*DD + coln] = f2bf2(v0, v1);
                    if (r1 < WW)
                        *(uint32_t*)&g_wc[((size_t)b*WW + r1)*DD + coln] = f2bf2(v2, v3);
                }
            }
        }
#pragma unroll
        for (int i = 0; i < 2; i++)
#pragma unroll
            for (int h = 0; h < 2; h++) {
                psq[i][h] += __shfl_xor_sync(0xffffffffu, psq[i][h], 1);
                psq[i][h] += __shfl_xor_sync(0xffffffffu, psq[i][h], 2);
            }
        if (tig == 0) {
#pragma unroll
            for (int i = 0; i < 2; i++) {
                sRed[(i*16 + g    )*8 + wid] = psq[i][0];
                sRed[(i*16 + g + 8)*8 + wid] = psq[i][1];
            }
        }
        __syncthreads();
        if (tid < WW) {
            float s = 0.f;
#pragma unroll
            for (int k = 0; k < 8; k++) s += sRed[tid*8 + k];
            g_fac[(size_t)b*WW + tid] = 1.f / (sqrtf(s) + 1e-8f);
        }
    }
}

// ---------------------------------------------------------------------------
// rar: dir==0 computes hig = masked mean in-kernel; dir==1 also emits the
// final sigmoid output (final_kernel fused).
// ---------------------------------------------------------------------------
__global__ void __launch_bounds__(256) rar_kernel(
        const int* __restrict__ lens,
        const float* __restrict__ qw, const float* __restrict__ qb,
        const float* __restrict__ vw, const float* __restrict__ vb,
        const __nv_bfloat16* __restrict__ kt, int dir,
        const float* __restrict__ ew, const float* __restrict__ eb,
        float* __restrict__ out)
{
    extern __shared__ float sm[];
    __nv_bfloat16* sMid = (__nv_bfloat16*)sm;
    float* sHig = sm + WW*SS/2;
    float* sRed = sHig + SS;
    float* sLog = sRed + WW*8;
    float* sWgt = sLog + WW;
    float* sMisc= sWgt + WW;

    const int b = blockIdx.x;
    const int c = b / NN;
    const int tid = threadIdx.x, lane = tid & 31, wid = tid >> 5;
    const int len = lens[c];

    {
        const uint4* gm = (const uint4*)(g_smid + (size_t)b*WW*SS);
        uint4* s4 = (uint4*)sMid;
        for (int i = tid; i < WW*SS/8; i += 256) s4[i] = gm[i];
    }
    __syncthreads();

    if (dir == 0) {
        float s = 0.f;
        for (int w = 0; w < len; w++) s += __bfloat162float(sMid[w*SS + tid]);
        sHig[tid] = s / (float)len;
    } else {
        sHig[tid] = g_higB[(size_t)b*SS + tid];
    }
    __syncthreads();

    float hv;
    {
        float acc = qb[tid];
        const float* wp = qw + tid;
#pragma unroll 4
        for (int s0 = 0; s0 < SS/4; s0++) {
            float4 h4 = *(const float4*)(sHig + s0*4);
            acc = fmaf(h4.x, wp[(size_t)(s0*4+0)*SS], acc);
            acc = fmaf(h4.y, wp[(size_t)(s0*4+1)*SS], acc);
            acc = fmaf(h4.z, wp[(size_t)(s0*4+2)*SS], acc);
            acc = fmaf(h4.w, wp[(size_t)(s0*4+3)*SS], acc);
        }
        hv = tanhf(acc) * vw[tid];
    }

    {
        const __nv_bfloat16* ktp = kt + (size_t)b*WW*SS + tid;
        float pv[WW];
#pragma unroll
        for (int w = 0; w < WW; w++)
            pv[w] = __bfloat162float(ktp[(size_t)w*SS]) * hv;
#pragma unroll
        for (int w = 0; w < WW; w++) {
            float v = warp_sum(pv[w]);
            if (lane == 0) sRed[w*8 + wid] = v;
        }
    }
    __syncthreads();
    if (tid < WW) {
        float s = 0.f;
#pragma unroll
        for (int k = 0; k < 8; k++) s += sRed[tid*8 + k];
        s += vb[0];
        if (tid >= len) s = -1e30f;
        sLog[tid] = s;
    }
    __syncthreads();
    if (tid == 0) {
        float m = -1e30f;
        for (int w = 0; w < WW; w++) m = fmaxf(m, sLog[w]);
        float s = 0.f;
        for (int w = 0; w < WW; w++) { float e = expf(sLog[w] - m); sWgt[w] = e; s += e; }
        float inv = 1.f / s;
        for (int w = 0; w < WW; w++) sWgt[w] *= inv;
    }
    __syncthreads();

    float o = 0.f;
#pragma unroll
    for (int w = 0; w < WW; w++)
        o = fmaf(sWgt[w], __bfloat162float(sMid[w*SS + tid]), o);
    float sq = warp_sum(o * o);
    if (lane == 0) sRed[wid] = sq;
    __syncthreads();
    if (tid == 0) {
        float tot = 0.f;
#pragma unroll
        for (int k = 0; k < 8; k++) tot += sRed[k];
        sMisc[0] = 1.f / (sqrtf(tot) + 1e-8f);
    }
    __syncthreads();

    if (dir == 0) {
        g_higB[(size_t)b*SS + tid] = o * sMisc[0];
    } else {
        // fused final: sim = sigmoid(dot(hig_final, ew) + eb)
        float hval = o * sMisc[0];
        float a = hval * ew[tid];
        a = warp_sum(a);
        if (lane == 0) sRed[wid] = a;
        __syncthreads();
        if (tid == 0) {
            float s = 0.f;
#pragma unroll
            for (int k = 0; k < 8; k++) s += sRed[k];
            float v = s + eb[0];
            int cc = b / NN, nn = b % NN;
            out[nn*CC + cc] = 1.f / (1.f + expf(-v));
        }
    }
}

// ---------------------------------------------------------------------------
extern "C" void kernel_launch(void* const* d_in, const int* in_sizes, int n_in,
                              void* d_out, int out_size)
{
    const float* img  = (const float*)d_in[0];
    const float* cap  = (const float*)d_in[1];
    const int*   lens = (const int*)  d_in[2];
    const float* alvw = (const float*)d_in[3];
    const float* alvb = (const float*)d_in[4];
    const float* qw   = (const float*)d_in[5];
    const float* qb   = (const float*)d_in[6];
    const float* kw   = (const float*)d_in[7];
    const float* kb   = (const float*)d_in[8];
    const float* vw   = (const float*)d_in[9];
    const float* vb   = (const float*)d_in[10];
    const float* smw1 = (const float*)d_in[11];
    const float* smb1 = (const float*)d_in[12];
    const float* smw2 = (const float*)d_in[13];
    const float* smb2 = (const float*)d_in[14];
    const float* mxw1 = (const float*)d_in[15];
    const float* mxb1 = (const float*)d_in[16];
    const float* mxw2 = (const float*)d_in[17];
    const float* mxb2 = (const float*)d_in[18];
    const float* ew   = (const float*)d_in[19];
    const float* eb   = (const float*)d_in[20];
    float* out = (float*)d_out;

    float *pFac, *pSmooth;
    __nv_bfloat16 *pH, *pWbf, *pWc, *pKt, *pQm, *pSmid;
    cudaGetSymbolAddress((void**)&pSmid, g_smid);
    cudaGetSymbolAddress((void**)&pQm,  g_qmb);
    cudaGetSymbolAddress((void**)&pWc,  g_wc);
    cudaGetSymbolAddress((void**)&pFac, g_fac);
    cudaGetSymbolAddress((void**)&pH,   g_h);
    cudaGetSymbolAddress((void**)&pWbf, g_wbf);
    cudaGetSymbolAddress((void**)&pKt,  g_kt);
    cudaGetSymbolAddress((void**)&pSmooth, g_smooth);

    const size_t ALV_SMEM = (size_t)(48*1032 + 32*1032) * 2
                          + (size_t)(RR*WW*2 + 32*8) * 4 + 32*28*4;
    const size_t RAR_SMEM = (size_t)(WW*SS/2 + SS + WW*8 + WW + WW + 32) * sizeof(float);
    const size_t SM_N256 = (size_t)(2*64*20 + 2*32*132)*4 + (64*8 + 64)*4;
    const size_t SM_N128 = (size_t)(2*64*20 + 2*32*68)*4 + (64*8 + 64)*4;

    cudaFuncSetAttribute(alv_kernel<0>, cudaFuncAttributeMaxDynamicSharedMemorySize, (int)ALV_SMEM);
    cudaFuncSetAttribute(alv_kernel<1>, cudaFuncAttributeMaxDynamicSharedMemorySize, (int)ALV_SMEM);
    cudaFuncSetAttribute(gemm_bf16<64,256,1024,256,1,0,1>, cudaFuncAttributeMaxDynamicSharedMemorySize, (int)SM_N256);
    cudaFuncSetAttribute(gemm_bf16<64,128,256,896,2,3,1>,  cudaFuncAttributeMaxDynamicSharedMemorySize, (int)SM_N128);
    cudaFuncSetAttribute(gemm_bf16<64,256,512,1024,2,2,1>, cudaFuncAttributeMaxDynamicSharedMemorySize, (int)SM_N256);
    cudaFuncSetAttribute(gemm_bf16<64,256,256,256,2,1,1>,  cudaFuncAttributeMaxDynamicSharedMemorySize, (int)SM_N256);

    const int B = CC * NN;
    const int MB64 = MTOT / 64;

    cvtw_all<<<(335872 + 255)/256, 256>>>(alvw, mxw2, kw, mxw1, smw1, pWbf);

    // ---- pass 0 ----
    alv_kernel<0><<<B, 256, ALV_SMEM>>>(img, cap, lens);
    gemm_bf16<64,256,1024,256,1,0,1><<<dim3(1,MB64), 256, SM_N256>>>(
        nullptr, pWc, pWbf + OFF_ALV0, alvb, nullptr, nullptr,
        nullptr, pSmid, nullptr, nullptr, cap, pFac);
    gemm_bf16<64,128,256,896,2,3,1><<<dim3(7,MB64), 256, SM_N128>>>(
        nullptr, pSmid, pWbf + OFF_WMLP, mxb1, smb1, kb,
        pSmooth, pH, nullptr, pKt, smb2, smw2);
    gemm_bf16<64,256,512,1024,2,2,1><<<dim3(4,MB64), 256, SM_N256>>>(
        nullptr, pH, pWbf + OFF_MX2, mxb2, nullptr, nullptr,
        nullptr, pQm, nullptr, nullptr, cap, nullptr);
    rar_kernel<<<B, 256, RAR_SMEM>>>(lens, qw, qb, vw, vb, pKt, 0, nullptr, nullptr, nullptr);

    // ---- pass 1 ----
    alv_kernel<1><<<B, 256, ALV_SMEM>>>(img, cap, lens);
    gemm_bf16<64,256,1024,256,1,0,1><<<dim3(1,MB64), 256, SM_N256>>>(
        nullptr, pWc, pWbf + OFF_ALV1, alvb + SS, nullptr, nullptr,
        nullptr, pSmid, nullptr, nullptr, cap, pFac);
    gemm_bf16<64,256,256,256,2,1,1><<<dim3(1,MB64), 256, SM_N256>>>(
        nullptr, pSmid, pWbf + OFF_KW1, kb + SS, nullptr, nullptr,
        nullptr, pKt, nullptr, nullptr, nullptr, nullptr);
    rar_kernel<<<B, 256, RAR_SMEM>>>(lens, qw + SS*SS, qb + SS, vw + SS, vb + 1, pKt, 1,
                                     ew, eb, out);
}

// round 15
// speedup vs baseline: 1.4923x; 1.0189x over previous
#include <cuda_runtime.h>
#include <cuda_bf16.h>
#include <math.h>
#include <stdint.h>

#define CC 48
#define NN 48
#define WW 24
#define RR 36
#define DD 1024
#define SS 256
#define MTOT (CC*NN*WW)   // 55296

// ---------------- scratch (device globals; no allocation allowed) ----------
__device__ __align__(16) __nv_bfloat16 g_smid[MTOT*SS];         // 28 MB
__device__ __align__(16) float g_smooth[MTOT];
__device__ __align__(16) __nv_bfloat16 g_qmb[(size_t)MTOT*DD];  // 113 MB
__device__ __align__(16) __nv_bfloat16 g_wc[(size_t)MTOT*DD];   // 113 MB
__device__ __align__(16) float g_fac[MTOT];
__device__ __align__(16) __nv_bfloat16 g_h[(size_t)MTOT*512];   // 56 MB
__device__ __align__(16) __nv_bfloat16 g_kt[(size_t)MTOT*SS];   // 28 MB
__device__ __align__(16) __nv_bfloat16 g_wbf[1507328];          // weights bf16
__device__ __align__(16) float g_higB[CC*NN*SS];

#define OFF_ALV0 0
#define OFF_ALV1 262144
#define OFF_MX2  524288
#define OFF_KW1  1048576
#define OFF_WMLP 1114112

__device__ __forceinline__ float warp_sum(float v) {
#pragma unroll
    for (int o = 16; o; o >>= 1) v += __shfl_xor_sync(0xffffffffu, v, o);
    return v;
}
__device__ __forceinline__ float warp_max(float v) {
#pragma unroll
    for (int o = 16; o; o >>= 1) v = fmaxf(v, __shfl_xor_sync(0xffffffffu, v, o));
    return v;
}
__device__ __forceinline__ uint32_t f2bf2(float lo, float hi) {
    uint32_t r; asm("cvt.rn.bf16x2.f32 %0, %1, %2;" : "=r"(r) : "f"(hi), "f"(lo)); return r;
}
__device__ __forceinline__ void ldsm4(uint32_t* r, uint32_t a) {
    asm volatile("ldmatrix.sync.aligned.m8n8.x4.shared.b16 {%0,%1,%2,%3},[%4];"
        : "=r"(r[0]),"=r"(r[1]),"=r"(r[2]),"=r"(r[3]) : "r"(a));
}
__device__ __forceinline__ void ldsm4t(uint32_t* r, uint32_t a) {
    asm volatile("ldmatrix.sync.aligned.m8n8.x4.trans.shared.b16 {%0,%1,%2,%3},[%4];"
        : "=r"(r[0]),"=r"(r[1]),"=r"(r[2]),"=r"(r[3]) : "r"(a));
}
__device__ __forceinline__ void mmabf(float* d, const uint32_t* a, const uint32_t* b) {
    asm volatile("mma.sync.aligned.m16n8k16.row.col.f32.bf16.bf16.f32 "
        "{%0,%1,%2,%3},{%4,%5,%6,%7},{%8,%9},{%0,%1,%2,%3};"
        : "+f"(d[0]),"+f"(d[1]),"+f"(d[2]),"+f"(d[3])
        : "r"(a[0]),"r"(a[1]),"r"(a[2]),"r"(a[3]),"r"(b[0]),"r"(b[1]));
}

// ---------------------------------------------------------------------------
// merged weight conversion (6 regions, one launch)
// ---------------------------------------------------------------------------
__global__ void cvtw_all(const float* __restrict__ alvw, const float* __restrict__ mxw2,
                         const float* __restrict__ kw,   const float* __restrict__ mxw1,
                         const float* __restrict__ smw1, __nv_bfloat16* __restrict__ wbf)
{
    int i = blockIdx.x * blockDim.x + threadIdx.x;
    const float* src; __nv_bfloat16* dst; int j; int ncols = 0, dstride = 0, dcol0 = 0;
    if (i < 131072)      { src = alvw;        dst = wbf + OFF_ALV0; j = i; }
    else if (i < 262144) { src = mxw2;        dst = wbf + OFF_MX2;  j = i - 131072; }
    else if (i < 278528) { src = kw + SS*SS;  dst = wbf + OFF_KW1;  j = i - 262144; }
    else if (i < 311296) { src = mxw1; dst = wbf + OFF_WMLP; j = i - 278528; ncols = 512; dstride = 896; dcol0 = 0; }
    else if (i < 319488) { src = smw1; dst = wbf + OFF_WMLP; j = i - 311296; ncols = 128; dstride = 896; dcol0 = 512; }
    else if (i < 335872) { src = kw;   dst = wbf + OFF_WMLP; j = i - 319488; ncols = 256; dstride = 896; dcol0 = 640; }
    else return;
    float4 v = *(const float4*)(src + (size_t)j*4);
    uint2 o; o.x = f2bf2(v.x, v.y); o.y = f2bf2(v.z, v.w);
    if (ncols == 0) {
        *(uint2*)(dst + (size_t)j*4) = o;
    } else {
        int row = (j*4) / ncols, col = (j*4) % ncols;
        *(uint2*)(dst + (size_t)row*dstride + dcol0 + col) = o;
    }
}

// ---------------------------------------------------------------------------
// bf16 m16n8k16 GEMM — R11 1-D warp tiling. AMODE 2 uses cp.async mainloop
// (NSTG=3 for N128, 2 for N256). AMODE 0/1 keep the manual 2-stage path.
// EPI 0: +bias, l2norm full 256 row. EPI 1: +bias, tanh.
// EPI 2: +bias, tanh, clip(+1), *cap. EPI 3: fused MLP (h / smooth / kt).
// ---------------------------------------------------------------------------
template<int M_BLK,int N_BLK,int K_DIM,int N_TOT,int AMODE,int EPI,int OUTBF>
__global__ void __launch_bounds__(256) gemm_bf16(
    const float* __restrict__ Af, const __nv_bfloat16* __restrict__ Ab,
    const __nv_bfloat16* __restrict__ Bw,
    const float* __restrict__ bias, const float* __restrict__ bias2, const float* __restrict__ bias3,
    float* __restrict__ Cf, __nv_bfloat16* __restrict__ Cb,
    __nv_bfloat16* __restrict__ Cb2, __nv_bfloat16* __restrict__ Cb3,
    const float* __restrict__ cap, const float* __restrict__ fac)
{
    constexpr int MT   = M_BLK/16;
    constexpr int NT   = N_BLK/64;
    constexpr int SAW  = 20;
    constexpr int SBW  = N_BLK/2 + 4;
    constexpr int ABUF = M_BLK*SAW;
    constexpr int BBUF = 32*SBW;
    constexpr int APASS = M_BLK/32;
    constexpr int BROWP = 2048/N_BLK;
    constexpr int BPASS = 32/BROWP;
    constexpr int KT   = K_DIM/32;
    constexpr int NSTG = (AMODE == 2 && N_BLK == 128) ? 3 : 2;

    extern __shared__ uint32_t dsm[];
    uint32_t* As = dsm;
    uint32_t* Bs = dsm + NSTG*ABUF;
    float* sRed  = (float*)(dsm + NSTG*(ABUF + BBUF));
    float* sFacR = sRed + M_BLK*8;

    const int m0 = blockIdx.y * M_BLK;
    const int n0 = blockIdx.x * N_BLK;
    const int tid = threadIdx.x, lane = tid & 31, wid = tid >> 5;
    const int g = lane >> 2, tig = lane & 3;
    const int wn0 = wid * (N_BLK/8);

    const int a_row = tid >> 3, a_c = (tid & 7) * 4;
    float facr[APASS]; int caprow[APASS];
    if (AMODE == 1) {
#pragma unroll
        for (int p = 0; p < APASS; p++) {
            int r = m0 + p*32 + a_row;
            facr[p] = fac[r];
            caprow[p] = (r/1152)*24 + (r%24);
        }
    }
    const int b_row = tid / (N_BLK/8), b_c = (tid % (N_BLK/8)) * 8;
    const __nv_bfloat16* Bptr = Bw + (size_t)b_row*N_TOT + n0 + b_c;

    uint32_t smA = (uint32_t)__cvta_generic_to_shared(As);
    uint32_t smB = (uint32_t)__cvta_generic_to_shared(Bs);

    float acc[MT][NT][4];
#pragma unroll
    for (int i = 0; i < MT; i++)
#pragma unroll
        for (int j = 0; j < NT; j++)
#pragma unroll
            for (int k = 0; k < 4; k++) acc[i][j][k] = 0.f;

    const uint32_t aoff = (lane & 15)*(SAW*4) + (lane >> 4)*16;
    const uint32_t boff = ((lane & 7) + ((lane >> 3) & 1)*8)*(SBW*4)
                        + (wn0 + (lane >> 4)*8)*2;

    auto computeKt = [&](int buf) {
        uint32_t Ab0 = smA + buf*(ABUF*4);
        uint32_t Bb0 = smB + buf*(BBUF*4);
#pragma unroll
        for (int ks = 0; ks < 2; ks++) {
            uint32_t af[MT][4], bf[NT][2];
#pragma unroll
            for (int i = 0; i < MT; i++)
                ldsm4(af[i], Ab0 + i*16*(SAW*4) + aoff + ks*32);
#pragma unroll
            for (int jp = 0; jp < NT/2; jp++) {
                uint32_t t[4];
                ldsm4t(t, Bb0 + ks*16*(SBW*4) + boff + jp*32);
                bf[2*jp][0] = t[0]; bf[2*jp][1] = t[1];
                bf[2*jp+1][0] = t[2]; bf[2*jp+1][1] = t[3];
            }
#pragma unroll
            for (int i = 0; i < MT; i++)
#pragma unroll
                for (int j = 0; j < NT; j++)
                    mmabf(acc[i][j], af[i], bf[j]);
        }
    };

    if constexpr (AMODE == 2) {
        // ---- cp.async mainloop ----
        auto cpStage = [&](int kt, int buf) {
#pragma unroll
            for (int p = 0; p < APASS; p++) {
                const __nv_bfloat16* src = Ab + (size_t)(m0 + p*32 + a_row)*K_DIM + kt*32 + a_c;
                uint32_t dst = smA + (uint32_t)(buf*ABUF + (p*32 + a_row)*SAW + (tid&7)*2)*4;
                asm volatile("cp.async.ca.shared.global [%0],[%1],8;" :: "r"(dst), "l"(src) : "memory");
            }
#pragma unroll
            for (int p = 0; p < BPASS; p++) {
                const __nv_bfloat16* src = Bptr + (size_t)(kt*32 + p*BROWP)*N_TOT;
                uint32_t dst = smB + (uint32_t)(buf*BBUF + (b_row + p*BROWP)*SBW + (tid % (N_BLK/8))*4)*4;
                asm volatile("cp.async.cg.shared.global [%0],[%1],16;" :: "r"(dst), "l"(src) : "memory");
            }
            asm volatile("cp.async.commit_group;" ::: "memory");
        };
        cpStage(0, 0);
        if (NSTG == 3) cpStage(1, 1);
        for (int kt = 0; kt < KT; kt++) {
            asm volatile("cp.async.wait_group %0;" :: "n"(NSTG - 2) : "memory");
            __syncthreads();
            if (kt + NSTG - 1 < KT) cpStage(kt + NSTG - 1, (kt + NSTG - 1) % NSTG);
            else asm volatile("cp.async.commit_group;" ::: "memory");
            computeKt(kt % NSTG);
        }
        __syncthreads();
    } else {
        // ---- manual 2-stage mainloop (proven R11 path) ----
        uint32_t areg[2*APASS]; uint4 breg[BPASS];
        auto loadA = [&](int kt) {
#pragma unroll
            for (int p = 0; p < APASS; p++) {
                int r = m0 + p*32 + a_row;
                if (AMODE == 0) {
                    float4 v = *(const float4*)(Af + (size_t)r*K_DIM + kt*32 + a_c);
                    areg[p*2]   = f2bf2(v.x, v.y);
                    areg[p*2+1] = f2bf2(v.z, v.w);
                } else {
                    uint2 wv2 = *(const uint2*)(Ab + (size_t)r*K_DIM + kt*32 + a_c);
                    float2 w01 = __bfloat1622float2(*(__nv_bfloat162*)&wv2.x);
                    float2 w23 = __bfloat1622float2(*(__nv_bfloat162*)&wv2.y);
                    float4 cv = *(const float4*)(cap + (size_t)caprow[p]*K_DIM + kt*32 + a_c);
                    float f = facr[p];
                    float s0 = cv.x - w01.x*f; s0 *= s0;
                    float s1 = cv.y - w01.y*f; s1 *= s1;
                    float s2 = cv.z - w23.x*f; s2 *= s2;
                    float s3 = cv.w - w23.y*f; s3 *= s3;
                    areg[p*2]   = f2bf2(s0, s1);
                    areg[p*2+1] = f2bf2(s2, s3);
                }
            }
        };
        auto stsA = [&](int buf) {
#pragma unroll
            for (int p = 0; p < APASS; p++)
                *(uint2*)(As + buf*ABUF + (p*32 + a_row)*SAW + (tid&7)*2) =
                    make_uint2(areg[p*2], areg[p*2+1]);
        };
        auto loadB = [&](int kt) {
#pragma unroll
            for (int p = 0; p < BPASS; p++)
                breg[p] = *(const uint4*)(Bptr + (size_t)(kt*32 + p*BROWP)*N_TOT);
        };
        auto stsB = [&](int buf) {
#pragma unroll
            for (int p = 0; p < BPASS; p++)
                *(uint4*)(Bs + buf*BBUF + (b_row + p*BROWP)*SBW + (tid % (N_BLK/8))*4) = breg[p];
        };

        loadA(0); loadB(0);
        stsA(0);  stsB(0);
        __syncthreads();
        for (int kt = 0; kt < KT; kt++) {
            if (kt + 1 < KT) { loadA(kt+1); loadB(kt+1); }
            computeKt(kt & 1);
            if (kt + 1 < KT) { stsA((kt+1)&1); stsB((kt+1)&1); }
            __syncthreads();
        }
    }

    if (EPI != 3) {
#pragma unroll
        for (int j = 0; j < NT; j++) {
            int coln = n0 + wn0 + j*8 + 2*tig;
            float b0 = bias[coln], b1 = bias[coln+1];
#pragma unroll
            for (int i = 0; i < MT; i++) {
                acc[i][j][0] += b0; acc[i][j][1] += b1;
                acc[i][j][2] += b0; acc[i][j][3] += b1;
            }
        }
    }

    if (EPI == 0) {
        float ps[MT][2];
#pragma unroll
        for (int i = 0; i < MT; i++) {
            ps[i][0] = 0.f; ps[i][1] = 0.f;
#pragma unroll
            for (int j = 0; j < NT; j++) {
                ps[i][0] += acc[i][j][0]*acc[i][j][0] + acc[i][j][1]*acc[i][j][1];
                ps[i][1] += acc[i][j][2]*acc[i][j][2] + acc[i][j][3]*acc[i][j][3];
            }
        }
#pragma unroll
        for (int i = 0; i < MT; i++)
#pragma unroll
            for (int h = 0; h < 2; h++) {
                ps[i][h] += __shfl_xor_sync(0xffffffffu, ps[i][h], 1);
                ps[i][h] += __shfl_xor_sync(0xffffffffu, ps[i][h], 2);
            }
        if (tig == 0) {
#pragma unroll
            for (int i = 0; i < MT; i++) {
                sRed[(i*16 + g    )*8 + wid] = ps[i][0];
                sRed[(i*16 + g + 8)*8 + wid] = ps[i][1];
            }
        }
        __syncthreads();
        if (tid < M_BLK) {
            float s = 0.f;
#pragma unroll
            for (int k = 0; k < 8; k++) s += sRed[tid*8 + k];
            sFacR[tid] = 1.f / (sqrtf(s) + 1e-8f);
        }
        __syncthreads();
#pragma unroll
        for (int i = 0; i < MT; i++) {
            float f0 = sFacR[i*16 + g], f1 = sFacR[i*16 + g + 8];
#pragma unroll
            for (int j = 0; j < NT; j++) {
                int coln = wn0 + j*8 + 2*tig;
                if (OUTBF) {
                    *(uint32_t*)&Cb[(size_t)(m0 + i*16 + g    )*N_TOT + coln] =
                        f2bf2(acc[i][j][0]*f0, acc[i][j][1]*f0);
                    *(uint32_t*)&Cb[(size_t)(m0 + i*16 + g + 8)*N_TOT + coln] =
                        f2bf2(acc[i][j][2]*f1, acc[i][j][3]*f1);
                } else {
                    *(float2*)&Cf[(size_t)(m0 + i*16 + g    )*N_TOT + coln] =
                        make_float2(acc[i][j][0]*f0, acc[i][j][1]*f0);
                    *(float2*)&Cf[(size_t)(m0 + i*16 + g + 8)*N_TOT + coln] =
                        make_float2(acc[i][j][2]*f1, acc[i][j][3]*f1);
                }
            }
        }
    } else if (EPI == 1) {
#pragma unroll
        for (int i = 0; i < MT; i++) {
            int r0 = m0 + i*16 + g, r1 = r0 + 8;
#pragma unroll
            for (int j = 0; j < NT; j++) {
                int coln = n0 + wn0 + j*8 + 2*tig;
                float v0 = tanhf(acc[i][j][0]), v1 = tanhf(acc[i][j][1]);
                float v2 = tanhf(acc[i][j][2]), v3 = tanhf(acc[i][j][3]);
                if (OUTBF) {
                    *(uint32_t*)&Cb[(size_t)r0*N_TOT + coln] = f2bf2(v0, v1);
                    *(uint32_t*)&Cb[(size_t)r1*N_TOT + coln] = f2bf2(v2, v3);
                } else {
                    *(float2*)&Cf[(size_t)r0*N_TOT + coln] = make_float2(v0, v1);
                    *(float2*)&Cf[(size_t)r1*N_TOT + coln] = make_float2(v2, v3);
                }
            }
        }
    } else if (EPI == 2) {
#pragma unroll
        for (int i = 0; i < MT; i++) {
            int r0 = m0 + i*16 + g, r1 = r0 + 8;
            int cr0 = (r0/1152)*24 + (r0%24);
            int cr1 = (r1/1152)*24 + (r1%24);
#pragma unroll
            for (int j = 0; j < NT; j++) {
                int coln = n0 + wn0 + j*8 + 2*tig;
                float m00 = fminf(fmaxf(tanhf(acc[i][j][0]) + 1.f, -1.f), 1.f);
                float m01 = fminf(fmaxf(tanhf(acc[i][j][1]) + 1.f, -1.f), 1.f);
                float m10 = fminf(fmaxf(tanhf(acc[i][j][2]) + 1.f, -1.f), 1.f);
                float m11 = fminf(fmaxf(tanhf(acc[i][j][3]) + 1.f, -1.f), 1.f);
                float2 c0 = *(const float2*)&cap[(size_t)cr0*DD + coln];
                float2 c1 = *(const float2*)&cap[(size_t)cr1*DD + coln];
                if (OUTBF) {
                    *(uint32_t*)&Cb[(size_t)r0*N_TOT + coln] = f2bf2(c0.x*m00, c0.y*m01);
                    *(uint32_t*)&Cb[(size_t)r1*N_TOT + coln] = f2bf2(c1.x*m10, c1.y*m11);
                } else {
                    *(float2*)&Cf[(size_t)r0*N_TOT + coln] = make_float2(c0.x*m00, c0.y*m01);
                    *(float2*)&Cf[(size_t)r1*N_TOT + coln] = make_float2(c1.x*m10, c1.y*m11);
                }
            }
        }
    } else {  // EPI 3
        if (n0 >= 512 && n0 < 640) {
            float pr[MT][2];
#pragma unroll
            for (int i = 0; i < MT; i++) { pr[i][0] = 0.f; pr[i][1] = 0.f; }
#pragma unroll
            for (int j = 0; j < NT; j++) {
                int cl = (n0 - 512) + wn0 + j*8 + 2*tig;
                float b0 = bias2[cl], b1 = bias2[cl+1];
                float w0 = fac[cl],  w1 = fac[cl+1];
#pragma unroll
                for (int i = 0; i < MT; i++) {
                    pr[i][0] += tanhf(acc[i][j][0] + b0)*w0 + tanhf(acc[i][j][1] + b1)*w1;
                    pr[i][1] += tanhf(acc[i][j][2] + b0)*w0 + tanhf(acc[i][j][3] + b1)*w1;
                }
            }
#pragma unroll
            for (int i = 0; i < MT; i++)
#pragma unroll
                for (int h = 0; h < 2; h++) {
                    pr[i][h] += __shfl_xor_sync(0xffffffffu, pr[i][h], 1);
                    pr[i][h] += __shfl_xor_sync(0xffffffffu, pr[i][h], 2);
                }
            if (tig == 0) {
#pragma unroll
                for (int i = 0; i < MT; i++) {
                    sRed[(i*16 + g    )*8 + wid] = pr[i][0];
                    sRed[(i*16 + g + 8)*8 + wid] = pr[i][1];
                }
            }
            __syncthreads();
            if (tid < M_BLK) {
                float s = 0.f;
#pragma unroll
                for (int k = 0; k < 8; k++) s += sRed[tid*8 + k];
                float v = s + cap[0] + 9.0f;
                Cf[m0 + tid] = v > 0.f ? v : 0.f;
            }
        } else {
            __nv_bfloat16* outp; const float* bp; int ostride, oc0;
            if (n0 < 512) { outp = Cb;  bp = bias;  ostride = 512; oc0 = n0; }
            else          { outp = Cb3; bp = bias3; ostride = 256; oc0 = n0 - 640; }
#pragma unroll
            for (int j = 0; j < NT; j++) {
                int cl = oc0 + wn0 + j*8 + 2*tig;
                float b0 = bp[cl], b1 = bp[cl+1];
#pragma unroll
                for (int i = 0; i < MT; i++) {
                    acc[i][j][0] += b0; acc[i][j][1] += b1;
                    acc[i][j][2] += b0; acc[i][j][3] += b1;
                }
            }
#pragma unroll
            for (int i = 0; i < MT; i++) {
                int r0 = m0 + i*16 + g, r1 = r0 + 8;
#pragma unroll
                for (int j = 0; j < NT; j++) {
                    int cl = oc0 + wn0 + j*8 + 2*tig;
                    *(uint32_t*)&outp[(size_t)r0*ostride + cl] =
                        f2bf2(tanhf(acc[i][j][0]), tanhf(acc[i][j][1]));
                    *(uint32_t*)&outp[(size_t)r1*ostride + cl] =
                        f2bf2(tanhf(acc[i][j][2]), tanhf(acc[i][j][3]));
                }
            }
        }
    }
}

// ---------------------------------------------------------------------------
// alv kernel: tensorized attn + wctx; parallelized fp32 softmax phases.
// ---------------------------------------------------------------------------
template<int PASS>
__global__ void __launch_bounds__(256) alv_kernel(
        const float* __restrict__ img, const float* __restrict__ cap,
        const int* __restrict__ lens)
{
    constexpr int ARS = 28;
    constexpr int IRS = 516;

    extern __shared__ float sm[];
    __nv_bfloat16* sImgBf = (__nv_bfloat16*)sm;            // 48 x 1032
    __nv_bfloat16* sQBf   = sImgBf + 48*1032;              // 32 x 1032
    float* sA   = (float*)(sQBf + 32*1032);                // RR*WW
    float* sAT  = sA + RR*WW;                              // WW*RR
    uint32_t* sAbfW = (uint32_t*)(sAT + WW*RR);            // 32*ARS
    float* sRed = (float*)(sAbfW + 32*ARS);                // 32*8
    __nv_bfloat16* sAbf = (__nv_bfloat16*)sAbfW;

    const int b = blockIdx.x;
    const int c = b / NN, n = b % NN;
    const int tid = threadIdx.x, lane = tid & 31, wid = tid >> 5;
    const int g = lane >> 2, tig = lane & 3;
    const int len = lens[c];

    {
        const float4* gi = (const float4*)(img + (size_t)n * RR * DD);
        for (int i = tid; i < RR*DD/4; i += 256) {
            float4 v = gi[i];
            int r = (i*4) >> 10, col = (i*4) & 1023;
            uint2 o; o.x = f2bf2(v.x, v.y); o.y = f2bf2(v.z, v.w);
            *(uint2*)(sImgBf + (size_t)r*1032 + col) = o;
        }
        for (int i = tid; i < 12*256; i += 256) {
            int r = 36 + i/256, col = (i%256)*4;
            *(uint2*)(sImgBf + (size_t)r*1032 + col) = make_uint2(0,0);
        }
        if (PASS == 0) {
            const float4* gq = (const float4*)(cap + (size_t)c * WW * DD);
            for (int i = tid; i < WW*DD/4; i += 256) {
                float4 v = gq[i];
                int r = (i*4) >> 10, col = (i*4) & 1023;
                uint2 o; o.x = f2bf2(v.x, v.y); o.y = f2bf2(v.z, v.w);
                *(uint2*)(sQBf + (size_t)r*1032 + col) = o;
            }
        } else {
            const uint2* gq = (const uint2*)(g_qmb + (size_t)b * WW * DD);
            for (int i = tid; i < WW*DD/4; i += 256) {
                int r = (i*4) >> 10, col = (i*4) & 1023;
                *(uint2*)(sQBf + (size_t)r*1032 + col) = gq[i];
            }
        }
        for (int i = tid; i < 8*256; i += 256) {
            int r = 24 + i/256, col = (i%256)*4;
            *(uint2*)(sQBf + (size_t)r*1032 + col) = make_uint2(0,0);
        }
        for (int i = tid; i < 32*ARS; i += 256) sAbfW[i] = 0;
    }
    __syncthreads();

    // attn via bf16 mma (warps 0-5)
    if (wid < 6) {
        int mi = wid >> 1, ni = wid & 1;
        uint32_t smI = (uint32_t)__cvta_generic_to_shared(sImgBf);
        uint32_t smQ = (uint32_t)__cvta_generic_to_shared(sQBf);
        uint32_t aBase = smI + (mi*16 + (lane & 15))*(IRS*4) + (lane >> 4)*16;
        uint32_t bBase = smQ + (ni*16 + (lane & 15))*(IRS*4) + (lane >> 4)*16;
        float acc0[4] = {0,0,0,0}, acc1[4] = {0,0,0,0};
#pragma unroll 4
        for (int kk = 0; kk < 64; kk++) {
            uint32_t a[4], t[4];
            ldsm4(a, aBase + kk*32);
            ldsm4(t, bBase + kk*32);
            uint32_t b0[2] = {t[0], t[2]};
            uint32_t b1[2] = {t[1], t[3]};
            mmabf(acc0, a, b0);
            mmabf(acc1, a, b1);
        }
        int r0 = mi*16 + g, r1 = r0 + 8;
        int w0 = ni*16 + 2*tig;
        if (r0 < RR) {
            if (w0 < WW)     sA[r0*WW + w0]     = acc0[0];
            if (w0+1 < WW)   sA[r0*WW + w0+1]   = acc0[1];
            if (w0+8 < WW)   sA[r0*WW + w0+8]   = acc1[0];
            if (w0+9 < WW)   sA[r0*WW + w0+9]   = acc1[1];
        }
        if (r1 < RR) {
            if (w0 < WW)     sA[r1*WW + w0]     = acc0[2];
            if (w0+1 < WW)   sA[r1*WW + w0+1]   = acc0[3];
            if (w0+8 < WW)   sA[r1*WW + w0+8]   = acc1[2];
            if (w0+9 < WW)   sA[r1*WW + w0+9]   = acc1[3];
        }
    }
    __syncthreads();

    // phase 2a: leaky relu + mask + l2norm over words. 4 threads per region.
    {
        int r = tid >> 2, q = tid & 3;
        float vals[6];
        float ss = 0.f;
        if (r < RR) {
#pragma unroll
            for (int k = 0; k < 6; k++) {
                int w = q + k*4;
                float v = sA[r*WW + w];
                v = (v >= 0.f) ? v : 0.1f * v;
                if (w >= len) v = 0.f;
                vals[k] = v;
                ss += v * v;
            }
        }
        ss += __shfl_xor_sync(0xffffffffu, ss, 1);
        ss += __shfl_xor_sync(0xffffffffu, ss, 2);
        if (r < RR) {
            float f = 1.f / (sqrtf(ss) + 1e-8f);
#pragma unroll
            for (int k = 0; k < 6; k++) sAT[(q + k*4)*RR + r] = vals[k] * f;
        }
    }
    __syncthreads();

    // phase 2b: softmax over regions -> bf16 A tile. 1 warp per 3 words.
    {
#pragma unroll
        for (int t = 0; t < 3; t++) {
            int w = wid*3 + t;
            float smo = (PASS == 0) ? 9.f : g_smooth[(size_t)b*WW + w];
            float v0 = (lane < RR)      ? sAT[w*RR + lane]      * smo : -1e30f;
            float v1 = (lane + 32 < RR) ? sAT[w*RR + lane + 32] * smo : -1e30f;
            float m = warp_max(fmaxf(v0, v1));
            float e0 = (lane < RR)      ? expf(v0 - m) : 0.f;
            float e1 = (lane + 32 < RR) ? expf(v1 - m) : 0.f;
            float s = warp_sum(e0 + e1);
            float inv = 1.f / s;
            if (lane < RR)      sAbf[w*(2*ARS) + lane]      = __float2bfloat16(e0 * inv);
            if (lane + 32 < RR) sAbf[w*(2*ARS) + lane + 32] = __float2bfloat16(e1 * inv);
        }
    }
    __syncthreads();

    // wctx = A(32x48) @ B(48x1024) via bf16 mma (8 warps)
    {
        uint32_t smAttn = (uint32_t)__cvta_generic_to_shared(sAbf);
        uint32_t smImgB = (uint32_t)__cvta_generic_to_shared(sImgBf);
        const uint32_t aoff = (lane & 15)*(ARS*4) + (lane >> 4)*16;
        const uint32_t bRowSel = ((lane & 7) + ((lane >> 3) & 1)*8)*(IRS*4);
        const uint32_t bColSel = (lane >> 4)*8;

        float psq[2][2] = {{0.f,0.f},{0.f,0.f}};
        for (int half = 0; half < 2; half++) {
            float acc[2][8][4];
#pragma unroll
            for (int i = 0; i < 2; i++)
#pragma unroll
                for (int j = 0; j < 8; j++)
#pragma unroll
                    for (int k = 0; k < 4; k++) acc[i][j][k] = 0.f;
#pragma unroll
            for (int ks = 0; ks < 3; ks++) {
                uint32_t af0[4], af1[4];
                ldsm4(af0, smAttn + aoff + ks*32);
                ldsm4(af1, smAttn + 16*(ARS*4) + aoff + ks*32);
#pragma unroll
                for (int jp = 0; jp < 4; jp++) {
                    int ncol = half*512 + wid*64 + jp*16 + bColSel;
                    uint32_t t[4];
                    ldsm4t(t, smImgB + ks*16*(IRS*4) + bRowSel + ncol*2);
                    mmabf(acc[0][2*jp],   af0, t);
                    mmabf(acc[0][2*jp+1], af0, t+2);
                    mmabf(acc[1][2*jp],   af1, t);
                    mmabf(acc[1][2*jp+1], af1, t+2);
                }
            }
#pragma unroll
            for (int i = 0; i < 2; i++) {
                int r0 = i*16 + g, r1 = r0 + 8;
#pragma unroll
                for (int j = 0; j < 8; j++) {
                    int coln = half*512 + wid*64 + j*8 + 2*tig;
                    float v0 = acc[i][j][0], v1 = acc[i][j][1];
                    float v2 = acc[i][j][2], v3 = acc[i][j][3];
                    psq[i][0] += v0*v0 + v1*v1;
                    psq[i][1] += v2*v2 + v3*v3;
                    if (r0 < WW)
                        *(uint32_t*)&g_wc[((size_t)b*WW + r0)*DD + coln] = f2bf2(v0, v1);
                    if (r1 < WW)
                        *(uint32_t*)&g_wc[((size_t)b*WW + r1)*DD + coln] = f2bf2(v2, v3);
                }
            }
        }
#pragma unroll
        for (int i = 0; i < 2; i++)
#pragma unroll
            for (int h = 0; h < 2; h++) {
                psq[i][h] += __shfl_xor_sync(0xffffffffu, psq[i][h], 1);
                psq[i][h] += __shfl_xor_sync(0xffffffffu, psq[i][h], 2);
            }
        if (tig == 0) {
#pragma unroll
            for (int i = 0; i < 2; i++) {
                sRed[(i*16 + g    )*8 + wid] = psq[i][0];
                sRed[(i*16 + g + 8)*8 + wid] = psq[i][1];
            }
        }
        __syncthreads();
        if (tid < WW) {
            float s = 0.f;
#pragma unroll
            for (int k = 0; k < 8; k++) s += sRed[tid*8 + k];
            g_fac[(size_t)b*WW + tid] = 1.f / (sqrtf(s) + 1e-8f);
        }
    }
}

// ---------------------------------------------------------------------------
// rar: dir==0 computes hig = masked mean in-kernel; dir==1 emits final sigmoid.
// ---------------------------------------------------------------------------
__global__ void __launch_bounds__(256) rar_kernel(
        const int* __restrict__ lens,
        const float* __restrict__ qw, const float* __restrict__ qb,
        const float* __restrict__ vw, const float* __restrict__ vb,
        const __nv_bfloat16* __restrict__ kt, int dir,
        const float* __restrict__ ew, const float* __restrict__ eb,
        float* __restrict__ out)
{
    extern __shared__ float sm[];
    __nv_bfloat16* sMid = (__nv_bfloat16*)sm;
    float* sHig = sm + WW*SS/2;
    float* sRed = sHig + SS;
    float* sLog = sRed + WW*8;
    float* sWgt = sLog + WW;
    float* sMisc= sWgt + WW;

    const int b = blockIdx.x;
    const int c = b / NN;
    const int tid = threadIdx.x, lane = tid & 31, wid = tid >> 5;
    const int len = lens[c];

    {
        const uint4* gm = (const uint4*)(g_smid + (size_t)b*WW*SS);
        uint4* s4 = (uint4*)sMid;
        for (int i = tid; i < WW*SS/8; i += 256) s4[i] = gm[i];
    }
    __syncthreads();

    if (dir == 0) {
        float s = 0.f;
        for (int w = 0; w < len; w++) s += __bfloat162float(sMid[w*SS + tid]);
        sHig[tid] = s / (float)len;
    } else {
        sHig[tid] = g_higB[(size_t)b*SS + tid];
    }
    __syncthreads();

    float hv;
    {
        float acc = qb[tid];
        const float* wp = qw + tid;
#pragma unroll 4
        for (int s0 = 0; s0 < SS/4; s0++) {
            float4 h4 = *(const float4*)(sHig + s0*4);
            acc = fmaf(h4.x, wp[(size_t)(s0*4+0)*SS], acc);
            acc = fmaf(h4.y, wp[(size_t)(s0*4+1)*SS], acc);
            acc = fmaf(h4.z, wp[(size_t)(s0*4+2)*SS], acc);
            acc = fmaf(h4.w, wp[(size_t)(s0*4+3)*SS], acc);
        }
        hv = tanhf(acc) * vw[tid];
    }

    {
        const __nv_bfloat16* ktp = kt + (size_t)b*WW*SS + tid;
        float pv[WW];
#pragma unroll
        for (int w = 0; w < WW; w++)
            pv[w] = __bfloat162float(ktp[(size_t)w*SS]) * hv;
#pragma unroll
        for (int w = 0; w < WW; w++) {
            float v = warp_sum(pv[w]);
            if (lane == 0) sRed[w*8 + wid] = v;
        }
    }
    __syncthreads();
    if (tid < WW) {
        float s = 0.f;
#pragma unroll
        for (int k = 0; k < 8; k++) s += sRed[tid*8 + k];
        s += vb[0];
        if (tid >= len) s = -1e30f;
        sLog[tid] = s;
    }
    __syncthreads();
    if (tid == 0) {
        float m = -1e30f;
        for (int w = 0; w < WW; w++) m = fmaxf(m, sLog[w]);
        float s = 0.f;
        for (int w = 0; w < WW; w++) { float e = expf(sLog[w] - m); sWgt[w] = e; s += e; }
        float inv = 1.f / s;
        for (int w = 0; w < WW; w++) sWgt[w] *= inv;
    }
    __syncthreads();

    float o = 0.f;
#pragma unroll
    for (int w = 0; w < WW; w++)
        o = fmaf(sWgt[w], __bfloat162float(sMid[w*SS + tid]), o);
    float sq = warp_sum(o * o);
    if (lane == 0) sRed[wid] = sq;
    __syncthreads();
    if (tid == 0) {
        float tot = 0.f;
#pragma unroll
        for (int k = 0; k < 8; k++) tot += sRed[k];
        sMisc[0] = 1.f / (sqrtf(tot) + 1e-8f);
    }
    __syncthreads();

    if (dir == 0) {
        g_higB[(size_t)b*SS + tid] = o * sMisc[0];
    } else {
        float hval = o * sMisc[0];
        float a = hval * ew[tid];
        a = warp_sum(a);
        if (lane == 0) sRed[wid] = a;
        __syncthreads();
        if (tid == 0) {
            float s = 0.f;
#pragma unroll
            for (int k = 0; k < 8; k++) s += sRed[k];
            float v = s + eb[0];
            int cc = b / NN, nn = b % NN;
            out[nn*CC + cc] = 1.f / (1.f + expf(-v));
        }
    }
}

// ---------------------------------------------------------------------------
extern "C" void kernel_launch(void* const* d_in, const int* in_sizes, int n_in,
                              void* d_out, int out_size)
{
    const float* img  = (const float*)d_in[0];
    const float* cap  = (const float*)d_in[1];
    const int*   lens = (const int*)  d_in[2];
    const float* alvw = (const float*)d_in[3];
    const float* alvb = (const float*)d_in[4];
    const float* qw   = (const float*)d_in[5];
    const float* qb   = (const float*)d_in[6];
    const float* kw   = (const float*)d_in[7];
    const float* kb   = (const float*)d_in[8];
    const float* vw   = (const float*)d_in[9];
    const float* vb   = (const float*)d_in[10];
    const float* smw1 = (const float*)d_in[11];
    const float* smb1 = (const float*)d_in[12];
    const float* smw2 = (const float*)d_in[13];
    const float* smb2 = (const float*)d_in[14];
    const float* mxw1 = (const float*)d_in[15];
    const float* mxb1 = (const float*)d_in[16];
    const float* mxw2 = (const float*)d_in[17];
    const float* mxb2 = (const float*)d_in[18];
    const float* ew   = (const float*)d_in[19];
    const float* eb   = (const float*)d_in[20];
    float* out = (float*)d_out;

    float *pFac, *pSmooth;
    __nv_bfloat16 *pH, *pWbf, *pWc, *pKt, *pQm, *pSmid;
    cudaGetSymbolAddress((void**)&pSmid, g_smid);
    cudaGetSymbolAddress((void**)&pQm,  g_qmb);
    cudaGetSymbolAddress((void**)&pWc,  g_wc);
    cudaGetSymbolAddress((void**)&pFac, g_fac);
    cudaGetSymbolAddress((void**)&pH,   g_h);
    cudaGetSymbolAddress((void**)&pWbf, g_wbf);
    cudaGetSymbolAddress((void**)&pKt,  g_kt);
    cudaGetSymbolAddress((void**)&pSmooth, g_smooth);

    const size_t ALV_SMEM = (size_t)(48*1032 + 32*1032) * 2
                          + (size_t)(RR*WW*2 + 32*8) * 4 + 32*28*4;
    const size_t RAR_SMEM = (size_t)(WW*SS/2 + SS + WW*8 + WW + WW + 32) * sizeof(float);
    // smem = NSTG*(ABUF+BBUF)*4 + (M_BLK*8 + M_BLK)*4
    const size_t SM_SIM  = (size_t)(2*(64*20 + 32*132))*4 + (64*9)*4;   // 46336 (N256, 2stg)
    const size_t SM_MLP  = (size_t)(3*(64*20 + 32*68))*4  + (64*9)*4;   // 43776 (N128, 3stg)
    const size_t SM_N256A= (size_t)(2*(64*20 + 32*132))*4 + (64*9)*4;   // 46336 (N256, 2stg async)

    cudaFuncSetAttribute(alv_kernel<0>, cudaFuncAttributeMaxDynamicSharedMemorySize, (int)ALV_SMEM);
    cudaFuncSetAttribute(alv_kernel<1>, cudaFuncAttributeMaxDynamicSharedMemorySize, (int)ALV_SMEM);
    cudaFuncSetAttribute(gemm_bf16<64,256,1024,256,1,0,1>, cudaFuncAttributeMaxDynamicSharedMemorySize, (int)SM_SIM);
    cudaFuncSetAttribute(gemm_bf16<64,128,256,896,2,3,1>,  cudaFuncAttributeMaxDynamicSharedMemorySize, (int)SM_MLP);
    cudaFuncSetAttribute(gemm_bf16<64,256,512,1024,2,2,1>, cudaFuncAttributeMaxDynamicSharedMemorySize, (int)SM_N256A);
    cudaFuncSetAttribute(gemm_bf16<64,256,256,256,2,1,1>,  cudaFuncAttributeMaxDynamicSharedMemorySize, (int)SM_N256A);

    const int B = CC * NN;
    const int MB64 = MTOT / 64;

    cvtw_all<<<(335872 + 255)/256, 256>>>(alvw, mxw2, kw, mxw1, smw1, pWbf);

    // ---- pass 0 ----
    alv_kernel<0><<<B, 256, ALV_SMEM>>>(img, cap, lens);
    gemm_bf16<64,256,1024,256,1,0,1><<<dim3(1,MB64), 256, SM_SIM>>>(
        nullptr, pWc, pWbf + OFF_ALV0, alvb, nullptr, nullptr,
        nullptr, pSmid, nullptr, nullptr, cap, pFac);
    gemm_bf16<64,128,256,896,2,3,1><<<dim3(7,MB64), 256, SM_MLP>>>(
        nullptr, pSmid, pWbf + OFF_WMLP, mxb1, smb1, kb,
        pSmooth, pH, nullptr, pKt, smb2, smw2);
    gemm_bf16<64,256,512,1024,2,2,1><<<dim3(4,MB64), 256, SM_N256A>>>(
        nullptr, pH, pWbf + OFF_MX2, mxb2, nullptr, nullptr,
        nullptr, pQm, nullptr, nullptr, cap, nullptr);
    rar_kernel<<<B, 256, RAR_SMEM>>>(lens, qw, qb, vw, vb, pKt, 0, nullptr, nullptr, nullptr);

    // ---- pass 1 ----
    alv_kernel<1><<<B, 256, ALV_SMEM>>>(img, cap, lens);
    gemm_bf16<64,256,1024,256,1,0,1><<<dim3(1,MB64), 256, SM_SIM>>>(
        nullptr, pWc, pWbf + OFF_ALV1, alvb + SS, nullptr, nullptr,
        nullptr, pSmid, nullptr, nullptr, cap, pFac);
    gemm_bf16<64,256,256,256,2,1,1><<<dim3(1,MB64), 256, SM_N256A>>>(
        nullptr, pSmid, pWbf + OFF_KW1, kb + SS, nullptr, nullptr,
        nullptr, pKt, nullptr, nullptr, nullptr, nullptr);
    rar_kernel<<<B, 256, RAR_SMEM>>>(lens, qw + SS*SS, qb + SS, vw + SS, vb + 1, pKt, 1,
                                     ew, eb, out);
}